// round 1
// baseline (speedup 1.0000x reference)
#include <cuda_runtime.h>
#include <math.h>

#define Bv 32
#define Sv 128
#define Dv 300
#define VOC 20000
#define Kv 8
#define RROWS 4096      // B*S
#define G4 1200         // 4*D
#define ESTRIDE 20004   // padded row stride for logits/exp scratch (mult of 4)

// ---------------- scratch (static device globals; no allocations) ------------
__device__ float g_X[RROWS * Dv];                       // words @ W
__device__ float g_E[(size_t)RROWS * ESTRIDE];          // logits -> exp(l - max)
__device__ float g_rowsum[RROWS];
__device__ float g_V[RROWS * Dv];
__device__ float g_XI[(size_t)RROWS * G4];              // V @ lstm_Wih^T + bih
__device__ float g_h[Bv * Dv];
__device__ float g_c[Bv * Dv];
__device__ float g_gates[Bv * G4];
__device__ float g_H[Bv * Kv * Dv];

__device__ __forceinline__ float sigmoidf_(float x) {
    return 1.0f / (1.0f + __expf(-x));
}

// warp-cooperative dot of two 300-float vectors (w: global, hs: shared).
// Result valid on lane 0.
__device__ __forceinline__ float warp_dot300(const float* __restrict__ w,
                                             const float* hs, int lane) {
    float4 a0 = *(const float4*)(w + lane * 4);
    float4 b0 = *(const float4*)(hs + lane * 4);
    float s = a0.x * b0.x + a0.y * b0.y + a0.z * b0.z + a0.w * b0.w;
    float4 a1 = *(const float4*)(w + 128 + lane * 4);
    float4 b1 = *(const float4*)(hs + 128 + lane * 4);
    s += a1.x * b1.x + a1.y * b1.y + a1.z * b1.z + a1.w * b1.w;
    if (lane < 11) {
        float4 a2 = *(const float4*)(w + 256 + lane * 4);
        float4 b2 = *(const float4*)(hs + 256 + lane * 4);
        s += a2.x * b2.x + a2.y * b2.y + a2.z * b2.z + a2.w * b2.w;
    }
#pragma unroll
    for (int off = 16; off > 0; off >>= 1)
        s += __shfl_down_sync(0xffffffffu, s, off);
    return s;
}

// ---------------- X = words @ W  (4096x300 @ 300x300) ------------------------
__global__ void k_X(const float* __restrict__ words, const float* __restrict__ W,
                    float* __restrict__ X) {
    __shared__ __align__(16) float ws[16 * Dv];
    int r0 = blockIdx.x * 16;
    int tid = threadIdx.x;  // 320
    for (int idx = tid; idx < 16 * Dv; idx += 320)
        ws[idx] = words[(size_t)r0 * Dv + idx];
    __syncthreads();
    if (tid >= Dv) return;
    float acc[16];
#pragma unroll
    for (int r = 0; r < 16; r++) acc[r] = 0.f;
    for (int d = 0; d < Dv; d++) {
        float w = W[d * Dv + tid];
#pragma unroll
        for (int r = 0; r < 16; r++) acc[r] += ws[r * Dv + d] * w;
    }
#pragma unroll
    for (int r = 0; r < 16; r++) X[(size_t)(r0 + r) * Dv + tid] = acc[r];
}

// ---------------- NT slab GEMM: C[m,n] = dot(A[m,0:300], B[n,0:300]) ---------
// Full K=300 slabs of A (64 rows) and B (64 rows) in shared; 64x64 tile,
// 256 threads, 4x4 micro-tile. Optional alt row for n == N-1 (default_embed)
// and optional bias added at store.
#define SLAB_PITCH 68
#define SLAB_SMEM (2 * Dv * SLAB_PITCH * 4)

__global__ __launch_bounds__(256, 1) void gemm_nt_slab(
    const float* __restrict__ A, const float* __restrict__ Bm,
    const float* __restrict__ alt, const float* __restrict__ bias,
    float* __restrict__ C, int N, int ldC) {
    extern __shared__ float smem[];
    float* As = smem;                      // As[k*68 + m]
    float* Bs = smem + Dv * SLAB_PITCH;    // Bs[k*68 + n]
    int m0 = blockIdx.x * 64;
    int n0 = blockIdx.y * 64;
    int tid = threadIdx.x;

    // load A slab (vectorized, coalesced)
    for (int idx = tid; idx < 64 * 75; idx += 256) {
        int m = idx / 75, kq = (idx % 75) * 4;
        float4 v = *(const float4*)&A[(size_t)(m0 + m) * Dv + kq];
        As[(kq + 0) * SLAB_PITCH + m] = v.x;
        As[(kq + 1) * SLAB_PITCH + m] = v.y;
        As[(kq + 2) * SLAB_PITCH + m] = v.z;
        As[(kq + 3) * SLAB_PITCH + m] = v.w;
    }
    // load B slab (with N guard + optional alt row)
    for (int idx = tid; idx < 64 * 75; idx += 256) {
        int n = idx / 75, kq = (idx % 75) * 4;
        int gn = n0 + n;
        float4 v = make_float4(0.f, 0.f, 0.f, 0.f);
        if (gn < N) {
            const float* src = (alt != nullptr && gn == N - 1)
                                   ? alt
                                   : (Bm + (size_t)gn * Dv);
            v = *(const float4*)&src[kq];
        }
        Bs[(kq + 0) * SLAB_PITCH + n] = v.x;
        Bs[(kq + 1) * SLAB_PITCH + n] = v.y;
        Bs[(kq + 2) * SLAB_PITCH + n] = v.z;
        Bs[(kq + 3) * SLAB_PITCH + n] = v.w;
    }
    __syncthreads();

    int tx = tid & 15, ty = tid >> 4;
    float acc[4][4];
#pragma unroll
    for (int i = 0; i < 4; i++)
#pragma unroll
        for (int j = 0; j < 4; j++) acc[i][j] = 0.f;

#pragma unroll 4
    for (int k = 0; k < Dv; k++) {
        float4 a = *(const float4*)&As[k * SLAB_PITCH + ty * 4];
        float4 b = *(const float4*)&Bs[k * SLAB_PITCH + tx * 4];
        acc[0][0] += a.x * b.x; acc[0][1] += a.x * b.y; acc[0][2] += a.x * b.z; acc[0][3] += a.x * b.w;
        acc[1][0] += a.y * b.x; acc[1][1] += a.y * b.y; acc[1][2] += a.y * b.z; acc[1][3] += a.y * b.w;
        acc[2][0] += a.z * b.x; acc[2][1] += a.z * b.y; acc[2][2] += a.z * b.z; acc[2][3] += a.z * b.w;
        acc[3][0] += a.w * b.x; acc[3][1] += a.w * b.y; acc[3][2] += a.w * b.z; acc[3][3] += a.w * b.w;
    }

#pragma unroll
    for (int i = 0; i < 4; i++) {
        int gm = m0 + ty * 4 + i;
#pragma unroll
        for (int j = 0; j < 4; j++) {
            int gn = n0 + tx * 4 + j;
            if (gn < N) {
                float v = acc[i][j];
                if (bias != nullptr) v += bias[gn];
                C[(size_t)gm * ldC + gn] = v;
            }
        }
    }
}

// ---------------- row softmax -> unnormalized exp + rowsum -------------------
__global__ void k_softmax(float* __restrict__ E, float* __restrict__ rowsum) {
    int r = blockIdx.x;
    float* row = E + (size_t)r * ESTRIDE;
    int tid = threadIdx.x;  // 256
    __shared__ float red[256];
    float m = -1e30f;
    for (int v = tid; v < VOC + 1; v += 256) m = fmaxf(m, row[v]);
    red[tid] = m;
    __syncthreads();
    for (int s = 128; s > 0; s >>= 1) {
        if (tid < s) red[tid] = fmaxf(red[tid], red[tid + s]);
        __syncthreads();
    }
    m = red[0];
    __syncthreads();
    float sum = 0.f;
    for (int v = tid; v < VOC + 1; v += 256) {
        float e = __expf(row[v] - m);
        row[v] = e;
        sum += e;
    }
    red[tid] = sum;
    __syncthreads();
    for (int s = 128; s > 0; s >>= 1) {
        if (tid < s) red[tid] += red[tid + s];
        __syncthreads();
    }
    if (tid == 0) rowsum[r] = red[0];
}

// ---------------- V = (E[:,0:20000] @ vocab + E[:,20000]*words) / rowsum -----
// NN GEMM, M=4096, N=300, K=20000. 64x64 tile, BK=32, 256 threads, 4x4 micro.
__global__ __launch_bounds__(256) void k_gemm_v(
    const float* __restrict__ E, const float* __restrict__ vocab,
    const float* __restrict__ words, const float* __restrict__ rowsum,
    float* __restrict__ V) {
    __shared__ __align__(16) float As[32 * 68];  // As[k*68 + m]
    __shared__ __align__(16) float Bs[32 * 68];  // Bs[k*68 + n]
    int m0 = blockIdx.x * 64;
    int n0 = blockIdx.y * 64;
    int tid = threadIdx.x, tx = tid & 15, ty = tid >> 4;
    float acc[4][4];
#pragma unroll
    for (int i = 0; i < 4; i++)
#pragma unroll
        for (int j = 0; j < 4; j++) acc[i][j] = 0.f;

    for (int k0 = 0; k0 < VOC; k0 += 32) {
        // A: 64 rows x 32 k, float4 loads (512 float4s)
        for (int i = tid; i < 512; i += 256) {
            int m = i >> 3, ks = (i & 7) * 4;
            float4 a = *(const float4*)&E[(size_t)(m0 + m) * ESTRIDE + k0 + ks];
            As[(ks + 0) * 68 + m] = a.x;
            As[(ks + 1) * 68 + m] = a.y;
            As[(ks + 2) * 68 + m] = a.z;
            As[(ks + 3) * 68 + m] = a.w;
        }
        // B: 32 k x 64 n, scalar coalesced with guard
        for (int i = tid; i < 2048; i += 256) {
            int k = i >> 6, n = i & 63;
            int gn = n0 + n;
            Bs[k * 68 + n] = (gn < Dv) ? vocab[(size_t)(k0 + k) * Dv + gn] : 0.f;
        }
        __syncthreads();
#pragma unroll
        for (int k = 0; k < 32; k++) {
            float4 a = *(const float4*)&As[k * 68 + ty * 4];
            float4 b = *(const float4*)&Bs[k * 68 + tx * 4];
            acc[0][0] += a.x * b.x; acc[0][1] += a.x * b.y; acc[0][2] += a.x * b.z; acc[0][3] += a.x * b.w;
            acc[1][0] += a.y * b.x; acc[1][1] += a.y * b.y; acc[1][2] += a.y * b.z; acc[1][3] += a.y * b.w;
            acc[2][0] += a.z * b.x; acc[2][1] += a.z * b.y; acc[2][2] += a.z * b.z; acc[2][3] += a.z * b.w;
            acc[3][0] += a.w * b.x; acc[3][1] += a.w * b.y; acc[3][2] += a.w * b.z; acc[3][3] += a.w * b.w;
        }
        __syncthreads();
    }

#pragma unroll
    for (int i = 0; i < 4; i++) {
        int r = m0 + ty * 4 + i;
        float pl = E[(size_t)r * ESTRIDE + VOC];
        float inv = 1.0f / rowsum[r];
#pragma unroll
        for (int j = 0; j < 4; j++) {
            int n = n0 + tx * 4 + j;
            if (n < Dv)
                V[(size_t)r * Dv + n] =
                    (acc[i][j] + pl * words[(size_t)r * Dv + n]) * inv;
        }
    }
}

// ---------------- misc small kernels -----------------------------------------
__global__ void k_zero(float* h, float* c) {
    int i = blockIdx.x * blockDim.x + threadIdx.x;
    if (i < Bv * Dv) { h[i] = 0.f; c[i] = 0.f; }
}

// gates[b, r] = XI[(b*128+t), r] + bhh[r] + dot(Whh[r,:], h[b,:])
__global__ void k_lstm_gates(const float* __restrict__ XI,
                             const float* __restrict__ Whh,
                             const float* __restrict__ bhh,
                             const float* __restrict__ h,
                             const int* __restrict__ lengths, int t,
                             float* __restrict__ gates) {
    int b = blockIdx.y;
    if (t >= lengths[b]) return;
    int chunk = blockIdx.x;  // 0..7 -> rows [chunk*150, chunk*150+150)
    __shared__ __align__(16) float hs[Dv];
    int tid = threadIdx.x;  // 256
    for (int i = tid; i < Dv; i += 256) hs[i] = h[b * Dv + i];
    __syncthreads();
    int warp = tid >> 5, lane = tid & 31;
    const float* xrow = XI + (size_t)(b * Sv + t) * G4;
    int rbase = chunk * 150;
    for (int r = rbase + warp; r < rbase + 150; r += 8) {
        float s = warp_dot300(Whh + (size_t)r * Dv, hs, lane);
        if (lane == 0) gates[b * G4 + r] = xrow[r] + bhh[r] + s;
    }
}

__global__ void k_lstm_update(const float* __restrict__ gates,
                              const int* __restrict__ lengths, int t,
                              float* __restrict__ h, float* __restrict__ c) {
    int b = blockIdx.x;
    if (t >= lengths[b]) return;
    int tid = threadIdx.x;
    if (tid >= Dv) return;
    const float* g = gates + b * G4;
    float gi = sigmoidf_(g[tid]);
    float gf = sigmoidf_(g[Dv + tid]);
    float gg = tanhf(g[2 * Dv + tid]);
    float go = sigmoidf_(g[3 * Dv + tid]);
    float cn = gf * c[b * Dv + tid] + gi * gg;
    float hn = go * tanhf(cn);
    c[b * Dv + tid] = cn;
    h[b * Dv + tid] = hn;
}

// RNN readout: h := tanh(q@Wih^T + bih + h@Whh^T + bhh), 8 steps, H[b,k,:]
__global__ void k_rnn(const float* __restrict__ q, const float* __restrict__ Wih,
                      const float* __restrict__ Whh, const float* __restrict__ bih,
                      const float* __restrict__ bhh, float* __restrict__ H) {
    int b = blockIdx.x;
    int tid = threadIdx.x;  // 320
    int warp = tid >> 5, lane = tid & 31;
    __shared__ __align__(16) float qs[Dv];
    __shared__ __align__(16) float hs[Dv];
    __shared__ float A[Dv];
    __shared__ float hn[Dv];
    for (int i = tid; i < Dv; i += 320) {
        qs[i] = q[b * Dv + i];
        hs[i] = 0.f;
    }
    __syncthreads();
    for (int r = warp; r < Dv; r += 10) {
        float s = warp_dot300(Wih + (size_t)r * Dv, qs, lane);
        if (lane == 0) A[r] = s + bih[r] + bhh[r];
    }
    __syncthreads();
    for (int k = 0; k < Kv; k++) {
        for (int r = warp; r < Dv; r += 10) {
            float s = warp_dot300(Whh + (size_t)r * Dv, hs, lane);
            if (lane == 0) hn[r] = tanhf(A[r] + s);
        }
        __syncthreads();
        for (int i = tid; i < Dv; i += 320) {
            float v = hn[i];
            hs[i] = v;
            H[(size_t)b * Kv * Dv + k * Dv + i] = v;
        }
        __syncthreads();
    }
}

// attention: scores=H.Vrow, masked softmax over s, R = P @ V
__global__ void k_attn(const float* __restrict__ H, const float* __restrict__ V,
                       const int* __restrict__ lengths, float* __restrict__ R) {
    int kk = blockIdx.x, b = blockIdx.y;
    int tid = threadIdx.x;  // 128 (one per s)
    __shared__ __align__(16) float Hs[Dv];
    __shared__ float rbuf[128];
    __shared__ float p[128];
    for (int i = tid; i < Dv; i += 128)
        Hs[i] = H[(size_t)b * Kv * Dv + kk * Dv + i];
    __syncthreads();
    int len = lengths[b];
    float sc = -1e30f;
    if (tid < len) {
        const float* vrow = V + (size_t)(b * Sv + tid) * Dv;
        float s = 0.f;
        for (int d = 0; d < Dv; d += 4) {
            float4 v4 = *(const float4*)&vrow[d];
            s += v4.x * Hs[d] + v4.y * Hs[d + 1] + v4.z * Hs[d + 2] + v4.w * Hs[d + 3];
        }
        sc = s;
    }
    rbuf[tid] = sc;
    __syncthreads();
    for (int s = 64; s > 0; s >>= 1) {
        if (tid < s) rbuf[tid] = fmaxf(rbuf[tid], rbuf[tid + s]);
        __syncthreads();
    }
    float m = rbuf[0];
    __syncthreads();
    float e = (tid < len) ? __expf(sc - m) : 0.f;
    rbuf[tid] = e;
    __syncthreads();
    for (int s = 64; s > 0; s >>= 1) {
        if (tid < s) rbuf[tid] += rbuf[tid + s];
        __syncthreads();
    }
    float denom = rbuf[0];
    __syncthreads();
    p[tid] = e / denom;
    __syncthreads();
    float* out = R + (size_t)(b * Kv + kk) * Dv;
    for (int d = tid; d < Dv; d += 128) {
        float s = 0.f;
        for (int si = 0; si < Sv; si++)
            s += p[si] * V[(size_t)(b * Sv + si) * Dv + d];
        out[d] = s;
    }
}

// ---------------- launch ------------------------------------------------------
extern "C" void kernel_launch(void* const* d_in, const int* in_sizes, int n_in,
                              void* d_out, int out_size) {
    const float* words    = (const float*)d_in[0];
    const int*   lengths  = (const int*)d_in[1];
    const float* vocab    = (const float*)d_in[2];
    const float* dembed   = (const float*)d_in[3];
    const float* W        = (const float*)d_in[4];
    const float* lstm_Wih = (const float*)d_in[5];
    const float* lstm_Whh = (const float*)d_in[6];
    const float* lstm_bih = (const float*)d_in[7];
    const float* lstm_bhh = (const float*)d_in[8];
    const float* rnn_Wih  = (const float*)d_in[9];
    const float* rnn_Whh  = (const float*)d_in[10];
    const float* rnn_bih  = (const float*)d_in[11];
    const float* rnn_bhh  = (const float*)d_in[12];
    float* out = (float*)d_out;

    float *pX, *pE, *pRS, *pV, *pXI, *ph, *pc, *pg, *pH;
    cudaGetSymbolAddress((void**)&pX, g_X);
    cudaGetSymbolAddress((void**)&pE, g_E);
    cudaGetSymbolAddress((void**)&pRS, g_rowsum);
    cudaGetSymbolAddress((void**)&pV, g_V);
    cudaGetSymbolAddress((void**)&pXI, g_XI);
    cudaGetSymbolAddress((void**)&ph, g_h);
    cudaGetSymbolAddress((void**)&pc, g_c);
    cudaGetSymbolAddress((void**)&pg, g_gates);
    cudaGetSymbolAddress((void**)&pH, g_H);

    cudaFuncSetAttribute(gemm_nt_slab,
                         cudaFuncAttributeMaxDynamicSharedMemorySize, SLAB_SMEM);

    // 1) X = words @ W
    k_X<<<RROWS / 16, 320>>>(words, W, pX);

    // 2) logits = X @ [vocab; default_embed]^T  -> g_E
    gemm_nt_slab<<<dim3(RROWS / 64, (VOC + 1 + 63) / 64), 256, SLAB_SMEM>>>(
        pX, vocab, dembed, nullptr, pE, VOC + 1, ESTRIDE);

    // 3) row softmax (unnormalized exp + rowsum)
    k_softmax<<<RROWS, 256>>>(pE, pRS);

    // 4) V = (E @ vocab + E_last * words) / rowsum
    k_gemm_v<<<dim3(RROWS / 64, 5), 256>>>(pE, vocab, words, pRS, pV);

    // 5) XI = V @ lstm_Wih^T + bih
    gemm_nt_slab<<<dim3(RROWS / 64, (G4 + 63) / 64), 256, SLAB_SMEM>>>(
        pV, lstm_Wih, nullptr, lstm_bih, pXI, G4, G4);

    // 6) LSTM over 128 steps (length-masked)
    k_zero<<<(Bv * Dv + 255) / 256, 256>>>(ph, pc);
    for (int t = 0; t < Sv; t++) {
        k_lstm_gates<<<dim3(8, Bv), 256>>>(pXI, lstm_Whh, lstm_bhh, ph, lengths,
                                           t, pg);
        k_lstm_update<<<Bv, 320>>>(pg, lengths, t, ph, pc);
    }

    // 7) RNN readout (q = final h)
    k_rnn<<<Bv, 320>>>(ph, rnn_Wih, rnn_Whh, rnn_bih, rnn_bhh, pH);

    // 8) attention -> output R (B,K,D)
    k_attn<<<dim3(Kv, Bv), 128>>>(pH, pV, lengths, out);
}

// round 3
// speedup vs baseline: 1.6433x; 1.6433x over previous
#include <cuda_runtime.h>
#include <cuda_bf16.h>
#include <math.h>

#define Bv 32
#define Sv 128
#define Dv 300
#define VOC 20000
#define Kv 8
#define RROWS 4096      // B*S
#define G4 1200         // 4*D
#define ESTRIDE 20004   // padded row stride for logits/exp scratch
#define NC_LSTM 75      // persistent LSTM CTAs (75*4 = 300 d's)

// ---------------- scratch (static device globals; no allocations) ------------
__device__ float g_X[RROWS * Dv];                       // words @ W
__device__ float g_E[(size_t)RROWS * ESTRIDE];          // logits -> exp(l - max)
__device__ float g_rowsum[RROWS];
__device__ float g_V[RROWS * Dv];
__device__ float g_XI[(size_t)RROWS * G4];              // V @ lstm_Wih^T + bih
__device__ float g_CT[(size_t)Dv * ESTRIDE];            // [vocab;dembed]^T
__device__ float g_WihT[Dv * G4];                       // lstm_Wih^T
__device__ float g_hbuf[2][Bv * Dv];                    // LSTM h double buffer
__device__ float g_H[Bv * Kv * Dv];
__device__ unsigned g_bar;

__device__ __forceinline__ float sigmoidf_(float x) {
    return 1.0f / (1.0f + __expf(-x));
}

// warp-cooperative dot of two 300-float vectors. Result valid on lane 0.
__device__ __forceinline__ float warp_dot300(const float* __restrict__ w,
                                             const float* hs, int lane) {
    float4 a0 = *(const float4*)(w + lane * 4);
    float4 b0 = *(const float4*)(hs + lane * 4);
    float s = a0.x * b0.x + a0.y * b0.y + a0.z * b0.z + a0.w * b0.w;
    float4 a1 = *(const float4*)(w + 128 + lane * 4);
    float4 b1 = *(const float4*)(hs + 128 + lane * 4);
    s += a1.x * b1.x + a1.y * b1.y + a1.z * b1.z + a1.w * b1.w;
    if (lane < 11) {
        float4 a2 = *(const float4*)(w + 256 + lane * 4);
        float4 b2 = *(const float4*)(hs + 256 + lane * 4);
        s += a2.x * b2.x + a2.y * b2.y + a2.z * b2.z + a2.w * b2.w;
    }
#pragma unroll
    for (int off = 16; off > 0; off >>= 1)
        s += __shfl_down_sync(0xffffffffu, s, off);
    return s;
}

// ---------------- bf16 split helpers -----------------------------------------
// x = hi + lo with hi,lo bf16; pack pairs along k into 32-bit words
__device__ __forceinline__ void split2(float x0, float x1, unsigned& hi,
                                       unsigned& lo) {
    __nv_bfloat16 h0 = __float2bfloat16_rn(x0);
    __nv_bfloat16 h1 = __float2bfloat16_rn(x1);
    float r0 = x0 - __bfloat162float(h0);
    float r1 = x1 - __bfloat162float(h1);
    __nv_bfloat16 l0 = __float2bfloat16_rn(r0);
    __nv_bfloat16 l1 = __float2bfloat16_rn(r1);
    hi = ((unsigned)__bfloat16_as_ushort(h1) << 16) | __bfloat16_as_ushort(h0);
    lo = ((unsigned)__bfloat16_as_ushort(l1) << 16) | __bfloat16_as_ushort(l0);
}

__device__ __forceinline__ void mma16(float* c, const unsigned* a,
                                      const unsigned* b) {
    asm volatile(
        "mma.sync.aligned.m16n8k16.row.col.f32.bf16.bf16.f32 "
        "{%0,%1,%2,%3}, {%4,%5,%6,%7}, {%8,%9}, {%0,%1,%2,%3};\n"
        : "+f"(c[0]), "+f"(c[1]), "+f"(c[2]), "+f"(c[3])
        : "r"(a[0]), "r"(a[1]), "r"(a[2]), "r"(a[3]), "r"(b[0]), "r"(b[1]));
}

__device__ __forceinline__ float4 ld4g(const float* p, int v) {
    if (v >= 4) return *(const float4*)p;
    float4 r = make_float4(0.f, 0.f, 0.f, 0.f);
    if (v > 0) r.x = p[0];
    if (v > 1) r.y = p[1];
    if (v > 2) r.z = p[2];
    return r;
}

// ---------------- transpose: dst[k][n] = src[n][k]  (+optional appended row) --
__global__ void k_transpose(const float* __restrict__ src, int nrows, int ncols,
                            const float* __restrict__ alt, float* __restrict__ dst,
                            int ldd) {
    __shared__ float t[32][33];
    int n0 = blockIdx.x * 32, k0 = blockIdx.y * 32;
    int x = threadIdx.x, y = threadIdx.y;  // 32x8
    int ntot = nrows + (alt ? 1 : 0);
    for (int i = y; i < 32; i += 8) {
        int n = n0 + i, k = k0 + x;
        float v = 0.f;
        if (k < ncols) {
            if (n < nrows) v = src[(size_t)n * ncols + k];
            else if (alt != nullptr && n == nrows) v = alt[k];
        }
        t[i][x] = v;
    }
    __syncthreads();
    for (int i = y; i < 32; i += 8) {
        int k = k0 + i, n = n0 + x;
        if (k < ncols && n < ntot)
            dst[(size_t)k * ldd + n] = t[x][i];
    }
}

// ---------------- split-bf16 NN GEMM: C[m][n] = sum_k A[m][k]*B[k][n] --------
// BM=128, BN=128, BK=16, 256 threads, 8 warps (2m x 4n), warp tile 64x32.
// 3-term split: Ahi*Bhi + Ahi*Blo + Alo*Bhi, fp32 accum (~fp32 accuracy).
// epi 0: C += bias (optional);  epi 1: V epilogue: (acc + pl*words)*inv
#define APITCH 12
#define BPITCH 136
__global__ __launch_bounds__(256) void mma_nn(
    const float* __restrict__ A, int lda,
    const float* __restrict__ Bt, int ldb,
    const float* __restrict__ bias,
    float* __restrict__ C, int ldc, int N, int K,
    int epi, const float* __restrict__ Emat,
    const float* __restrict__ rowsum, const float* __restrict__ words) {
    __shared__ unsigned Ahi[2][128][APITCH];  // [m][k2], k2 = bf16-pair index
    __shared__ unsigned Alo[2][128][APITCH];
    __shared__ unsigned Bhi[2][8][BPITCH];    // [k2][n]
    __shared__ unsigned Blo[2][8][BPITCH];
    int tid = threadIdx.x;
    int m0 = blockIdx.x * 128, n0 = blockIdx.y * 128;
    int lane = tid & 31, w = tid >> 5;
    int wm = (w >> 2) * 64, wn = (w & 3) * 32;

    float c[4][4][4];
#pragma unroll
    for (int i = 0; i < 4; i++)
#pragma unroll
        for (int j = 0; j < 4; j++)
#pragma unroll
            for (int q = 0; q < 4; q++) c[i][j][q] = 0.f;

    int am = tid >> 1, ahalf = tid & 1;      // A: row am, k chunk ahalf*8
    int bk2 = tid >> 5, bn4 = (tid & 31) * 4; // B: k-pair row bk2, n chunk bn4

    float4 pa0, pa1, pb0, pb1;
    const int nIter = (K + 15) >> 4;

    // prologue load (k0 = 0)
    {
        int kk = ahalf * 8;
        pa0 = ld4g(A + (size_t)(m0 + am) * lda + kk, K - kk);
        pa1 = ld4g(A + (size_t)(m0 + am) * lda + kk + 4, K - kk - 4);
        int gk0 = 2 * bk2, gk1 = gk0 + 1;
        int vn = N - (n0 + bn4);
        pb0 = (gk0 < K) ? ld4g(Bt + (size_t)gk0 * ldb + n0 + bn4, vn)
                        : make_float4(0, 0, 0, 0);
        pb1 = (gk1 < K) ? ld4g(Bt + (size_t)gk1 * ldb + n0 + bn4, vn)
                        : make_float4(0, 0, 0, 0);
    }

    for (int it = 0; it < nIter; ++it) {
        int buf = it & 1;
        // ---- store prefetched regs -> shared (split) ----
        {
            unsigned h[4], l[4];
            split2(pa0.x, pa0.y, h[0], l[0]);
            split2(pa0.z, pa0.w, h[1], l[1]);
            split2(pa1.x, pa1.y, h[2], l[2]);
            split2(pa1.z, pa1.w, h[3], l[3]);
            *(uint4*)&Ahi[buf][am][ahalf * 4] = make_uint4(h[0], h[1], h[2], h[3]);
            *(uint4*)&Alo[buf][am][ahalf * 4] = make_uint4(l[0], l[1], l[2], l[3]);
            // B pairs are across the two k rows at same n
            split2(pb0.x, pb1.x, h[0], l[0]);
            split2(pb0.y, pb1.y, h[1], l[1]);
            split2(pb0.z, pb1.z, h[2], l[2]);
            split2(pb0.w, pb1.w, h[3], l[3]);
            *(uint4*)&Bhi[buf][bk2][bn4] = make_uint4(h[0], h[1], h[2], h[3]);
            *(uint4*)&Blo[buf][bk2][bn4] = make_uint4(l[0], l[1], l[2], l[3]);
        }
        __syncthreads();

        // ---- issue next-stage global loads ----
        if (it + 1 < nIter) {
            int k0 = (it + 1) << 4;
            int kk = k0 + ahalf * 8;
            pa0 = ld4g(A + (size_t)(m0 + am) * lda + kk, K - kk);
            pa1 = ld4g(A + (size_t)(m0 + am) * lda + kk + 4, K - kk - 4);
            int gk0 = k0 + 2 * bk2, gk1 = gk0 + 1;
            int vn = N - (n0 + bn4);
            pb0 = (gk0 < K) ? ld4g(Bt + (size_t)gk0 * ldb + n0 + bn4, vn)
                            : make_float4(0, 0, 0, 0);
            pb1 = (gk1 < K) ? ld4g(Bt + (size_t)gk1 * ldb + n0 + bn4, vn)
                            : make_float4(0, 0, 0, 0);
        }

        // ---- compute one k16 step ----
        {
            unsigned ah[4][4], al[4][4];
            int k2a = lane & 3;
#pragma unroll
            for (int mi = 0; mi < 4; mi++) {
                int r = wm + mi * 16 + (lane >> 2);
                ah[mi][0] = Ahi[buf][r][k2a];
                ah[mi][1] = Ahi[buf][r + 8][k2a];
                ah[mi][2] = Ahi[buf][r][k2a + 4];
                ah[mi][3] = Ahi[buf][r + 8][k2a + 4];
                al[mi][0] = Alo[buf][r][k2a];
                al[mi][1] = Alo[buf][r + 8][k2a];
                al[mi][2] = Alo[buf][r][k2a + 4];
                al[mi][3] = Alo[buf][r + 8][k2a + 4];
            }
#pragma unroll
            for (int nj = 0; nj < 4; nj++) {
                int nb = wn + nj * 8 + (lane >> 2);
                unsigned bh[2], bl[2];
                bh[0] = Bhi[buf][k2a][nb];
                bh[1] = Bhi[buf][k2a + 4][nb];
                bl[0] = Blo[buf][k2a][nb];
                bl[1] = Blo[buf][k2a + 4][nb];
#pragma unroll
                for (int mi = 0; mi < 4; mi++) {
                    mma16(c[mi][nj], ah[mi], bh);
                    mma16(c[mi][nj], ah[mi], bl);
                    mma16(c[mi][nj], al[mi], bh);
                }
            }
        }
        __syncthreads();
    }

    // ---- epilogue ----
#pragma unroll
    for (int mi = 0; mi < 4; mi++) {
        int r1 = m0 + wm + mi * 16 + (lane >> 2);
        int r2 = r1 + 8;
        float pl1 = 0.f, pl2 = 0.f, inv1 = 1.f, inv2 = 1.f;
        if (epi == 1) {
            pl1 = Emat[(size_t)r1 * ESTRIDE + VOC];
            inv1 = 1.0f / rowsum[r1];
            pl2 = Emat[(size_t)r2 * ESTRIDE + VOC];
            inv2 = 1.0f / rowsum[r2];
        }
#pragma unroll
        for (int nj = 0; nj < 4; nj++) {
            int col0 = n0 + wn + nj * 8 + (lane & 3) * 2;
#pragma unroll
            for (int q = 0; q < 2; q++) {
                int col = col0 + q;
                if (col < N) {
                    float v1 = c[mi][nj][q];
                    float v2 = c[mi][nj][2 + q];
                    if (epi == 1) {
                        v1 = (v1 + pl1 * words[(size_t)r1 * Dv + col]) * inv1;
                        v2 = (v2 + pl2 * words[(size_t)r2 * Dv + col]) * inv2;
                    } else if (bias != nullptr) {
                        v1 += bias[col];
                        v2 += bias[col];
                    }
                    C[(size_t)r1 * ldc + col] = v1;
                    C[(size_t)r2 * ldc + col] = v2;
                }
            }
        }
    }
}

// ---------------- row softmax -> unnormalized exp + rowsum -------------------
__global__ void k_softmax(float* __restrict__ E, float* __restrict__ rowsum) {
    int r = blockIdx.x;
    float* row = E + (size_t)r * ESTRIDE;
    int tid = threadIdx.x;  // 256
    __shared__ float red[256];
    float m = -1e30f;
    for (int v = tid; v < VOC + 1; v += 256) m = fmaxf(m, row[v]);
    red[tid] = m;
    __syncthreads();
    for (int s = 128; s > 0; s >>= 1) {
        if (tid < s) red[tid] = fmaxf(red[tid], red[tid + s]);
        __syncthreads();
    }
    m = red[0];
    __syncthreads();
    float sum = 0.f;
    for (int v = tid; v < VOC + 1; v += 256) {
        float e = __expf(row[v] - m);
        row[v] = e;
        sum += e;
    }
    red[tid] = sum;
    __syncthreads();
    for (int s = 128; s > 0; s >>= 1) {
        if (tid < s) red[tid] += red[tid + s];
        __syncthreads();
    }
    if (tid == 0) rowsum[r] = red[0];
}

// ---------------- init for LSTM (reset barrier + h0) each launch -------------
__global__ void k_init() {
    int i = blockIdx.x * blockDim.x + threadIdx.x;
    if (i < Bv * Dv) g_hbuf[0][i] = 0.f;
    if (i == 0) g_bar = 0u;
}

// ---------------- persistent LSTM --------------------------------------------
__global__ __launch_bounds__(256) void k_lstm(const float* __restrict__ XI,
                                              const float* __restrict__ Whh,
                                              const float* __restrict__ bhh,
                                              const int* __restrict__ lengths) {
    extern __shared__ float sm[];
    float* Wsh = sm;                     // 16*300
    float* hsh = Wsh + 16 * 300;         // 32*300
    float* gsh = hsh + 32 * 300;         // 32*16
    float* csh = gsh + 32 * 16;          // 32*4
    float* bsh = csh + 32 * 4;           // 16
    int* lsh = (int*)(bsh + 16);         // 32

    int tid = threadIdx.x;
    int d0 = blockIdx.x * 4;
    int lane = tid & 31, w = tid >> 5;

    for (int i = tid; i < 16 * 300; i += 256) {
        int r = i / 300, cc = i - r * 300;
        Wsh[i] = Whh[(size_t)((r >> 2) * 300 + d0 + (r & 3)) * 300 + cc];
    }
    if (tid < 16) bsh[tid] = bhh[(tid >> 2) * 300 + d0 + (tid & 3)];
    if (tid < 32) lsh[tid] = lengths[tid];
    for (int i = tid; i < 128; i += 256) csh[i] = 0.f;
    __syncthreads();

    volatile unsigned* barp = &g_bar;

    for (int t = 0; t < Sv; ++t) {
        const float* hin = g_hbuf[t & 1];
        float* hout = g_hbuf[(t + 1) & 1];
        for (int i = tid; i < (32 * 300) / 4; i += 256)
            ((float4*)hsh)[i] = ((const float4*)hin)[i];
        for (int i = tid; i < 512; i += 256) {
            int b = i >> 4, r = i & 15;
            gsh[i] = XI[(size_t)((b << 7) + t) * G4 + (r >> 2) * 300 + d0 + (r & 3)] +
                     bsh[r];
        }
        __syncthreads();
        for (int i = w; i < 512; i += 8) {
            int b = i >> 4, r = i & 15;
            float s = warp_dot300(Wsh + r * 300, hsh + b * 300, lane);
            if (lane == 0) gsh[i] += s;
        }
        __syncthreads();
        if (tid < 128) {
            int b = tid >> 2, j = tid & 3;
            float hnew;
            if (t < lsh[b]) {
                float gi = sigmoidf_(gsh[b * 16 + j]);
                float gf = sigmoidf_(gsh[b * 16 + 4 + j]);
                float gg = tanhf(gsh[b * 16 + 8 + j]);
                float go = sigmoidf_(gsh[b * 16 + 12 + j]);
                float cn = gf * csh[tid] + gi * gg;
                csh[tid] = cn;
                hnew = go * tanhf(cn);
            } else {
                hnew = hsh[b * 300 + d0 + j];
            }
            hout[b * 300 + d0 + j] = hnew;
        }
        __threadfence();
        __syncthreads();
        if (tid == 0) {
            atomicAdd((unsigned*)&g_bar, 1u);
            unsigned target = (unsigned)(t + 1) * NC_LSTM;
            while (*barp < target) {
            }
            __threadfence();
        }
        __syncthreads();
    }
}

// ---------------- RNN readout -------------------------------------------------
__global__ void k_rnn(const float* __restrict__ q, const float* __restrict__ Wih,
                      const float* __restrict__ Whh, const float* __restrict__ bih,
                      const float* __restrict__ bhh, float* __restrict__ H) {
    int b = blockIdx.x;
    int tid = threadIdx.x;  // 320
    int warp = tid >> 5, lane = tid & 31;
    __shared__ __align__(16) float qs[Dv];
    __shared__ __align__(16) float hs[Dv];
    __shared__ float A[Dv];
    __shared__ float hn[Dv];
    for (int i = tid; i < Dv; i += 320) {
        qs[i] = q[b * Dv + i];
        hs[i] = 0.f;
    }
    __syncthreads();
    for (int r = warp; r < Dv; r += 10) {
        float s = warp_dot300(Wih + (size_t)r * Dv, qs, lane);
        if (lane == 0) A[r] = s + bih[r] + bhh[r];
    }
    __syncthreads();
    for (int k = 0; k < Kv; k++) {
        for (int r = warp; r < Dv; r += 10) {
            float s = warp_dot300(Whh + (size_t)r * Dv, hs, lane);
            if (lane == 0) hn[r] = tanhf(A[r] + s);
        }
        __syncthreads();
        for (int i = tid; i < Dv; i += 320) {
            float v = hn[i];
            hs[i] = v;
            H[(size_t)b * Kv * Dv + k * Dv + i] = v;
        }
        __syncthreads();
    }
}

// ---------------- attention ---------------------------------------------------
__global__ void k_attn(const float* __restrict__ H, const float* __restrict__ V,
                       const int* __restrict__ lengths, float* __restrict__ R) {
    int kk = blockIdx.x, b = blockIdx.y;
    int tid = threadIdx.x;  // 128
    __shared__ __align__(16) float Hs[Dv];
    __shared__ float rbuf[128];
    __shared__ float p[128];
    for (int i = tid; i < Dv; i += 128)
        Hs[i] = H[(size_t)b * Kv * Dv + kk * Dv + i];
    __syncthreads();
    int len = lengths[b];
    float sc = -1e30f;
    if (tid < len) {
        const float* vrow = V + (size_t)(b * Sv + tid) * Dv;
        float s = 0.f;
        for (int d = 0; d < Dv; d += 4) {
            float4 v4 = *(const float4*)&vrow[d];
            s += v4.x * Hs[d] + v4.y * Hs[d + 1] + v4.z * Hs[d + 2] + v4.w * Hs[d + 3];
        }
        sc = s;
    }
    rbuf[tid] = sc;
    __syncthreads();
    for (int s = 64; s > 0; s >>= 1) {
        if (tid < s) rbuf[tid] = fmaxf(rbuf[tid], rbuf[tid + s]);
        __syncthreads();
    }
    float m = rbuf[0];
    __syncthreads();
    float e = (tid < len) ? __expf(sc - m) : 0.f;
    rbuf[tid] = e;
    __syncthreads();
    for (int s = 64; s > 0; s >>= 1) {
        if (tid < s) rbuf[tid] += rbuf[tid + s];
        __syncthreads();
    }
    float denom = rbuf[0];
    __syncthreads();
    p[tid] = e / denom;
    __syncthreads();
    float* out = R + (size_t)(b * Kv + kk) * Dv;
    for (int d = tid; d < Dv; d += 128) {
        float s = 0.f;
        for (int si = 0; si < Sv; si++)
            s += p[si] * V[(size_t)(b * Sv + si) * Dv + d];
        out[d] = s;
    }
}

// ---------------- launch ------------------------------------------------------
extern "C" void kernel_launch(void* const* d_in, const int* in_sizes, int n_in,
                              void* d_out, int out_size) {
    const float* words    = (const float*)d_in[0];
    const int*   lengths  = (const int*)d_in[1];
    const float* vocab    = (const float*)d_in[2];
    const float* dembed   = (const float*)d_in[3];
    const float* W        = (const float*)d_in[4];
    const float* lstm_Wih = (const float*)d_in[5];
    const float* lstm_Whh = (const float*)d_in[6];
    const float* lstm_bih = (const float*)d_in[7];
    const float* lstm_bhh = (const float*)d_in[8];
    const float* rnn_Wih  = (const float*)d_in[9];
    const float* rnn_Whh  = (const float*)d_in[10];
    const float* rnn_bih  = (const float*)d_in[11];
    const float* rnn_bhh  = (const float*)d_in[12];
    float* out = (float*)d_out;

    float *pX, *pE, *pRS, *pV, *pXI, *pCT, *pWT, *pH, *pHB;
    cudaGetSymbolAddress((void**)&pX, g_X);
    cudaGetSymbolAddress((void**)&pE, g_E);
    cudaGetSymbolAddress((void**)&pRS, g_rowsum);
    cudaGetSymbolAddress((void**)&pV, g_V);
    cudaGetSymbolAddress((void**)&pXI, g_XI);
    cudaGetSymbolAddress((void**)&pCT, g_CT);
    cudaGetSymbolAddress((void**)&pWT, g_WihT);
    cudaGetSymbolAddress((void**)&pH, g_H);
    cudaGetSymbolAddress((void**)&pHB, g_hbuf);

    cudaFuncSetAttribute(k_lstm, cudaFuncAttributeMaxDynamicSharedMemorySize,
                         61440);

    // 0) transposes: CT = [vocab; dembed]^T (300x20001), WihT (300x1200)
    k_transpose<<<dim3((VOC + 1 + 31) / 32, (Dv + 31) / 32), dim3(32, 8)>>>(
        vocab, VOC, Dv, dembed, pCT, ESTRIDE);
    k_transpose<<<dim3((G4 + 31) / 32, (Dv + 31) / 32), dim3(32, 8)>>>(
        lstm_Wih, G4, Dv, nullptr, pWT, G4);

    // 1) X = words @ W
    mma_nn<<<dim3(RROWS / 128, (Dv + 127) / 128), 256>>>(
        words, Dv, W, Dv, nullptr, pX, Dv, Dv, Dv, 0, nullptr, nullptr, nullptr);

    // 2) logits = X @ CT  -> g_E  (N=20001)
    mma_nn<<<dim3(RROWS / 128, (VOC + 1 + 127) / 128), 256>>>(
        pX, Dv, pCT, ESTRIDE, nullptr, pE, ESTRIDE, VOC + 1, Dv, 0, nullptr,
        nullptr, nullptr);

    // 3) row softmax (unnormalized exp + rowsum)
    k_softmax<<<RROWS, 256>>>(pE, pRS);

    // 4) V = (E @ vocab + pl*words) / rowsum
    mma_nn<<<dim3(RROWS / 128, (Dv + 127) / 128), 256>>>(
        pE, ESTRIDE, vocab, Dv, nullptr, pV, Dv, Dv, VOC, 1, pE, pRS, words);

    // 5) XI = V @ WihT + bih  (N=1200)
    mma_nn<<<dim3(RROWS / 128, (G4 + 127) / 128), 256>>>(
        pV, Dv, pWT, G4, lstm_bih, pXI, G4, G4, Dv, 0, nullptr, nullptr, nullptr);

    // 6) persistent LSTM (128 steps, device-wide barrier)
    k_init<<<(Bv * Dv + 255) / 256, 256>>>();
    k_lstm<<<NC_LSTM, 256, 61440>>>(pXI, lstm_Whh, lstm_bhh, lengths);

    // 7) RNN readout (q = final h, in g_hbuf[0] after 128 steps)
    k_rnn<<<Bv, 320>>>(pHB, rnn_Wih, rnn_Whh, rnn_bih, rnn_bhh, pH);

    // 8) attention -> output R (B,K,D)
    k_attn<<<dim3(Kv, Bv), 128>>>(pH, pV, lengths, out);
}

// round 4
// speedup vs baseline: 1.8251x; 1.1106x over previous
#include <cuda_runtime.h>
#include <cuda_bf16.h>
#include <math.h>

#define Bv 32
#define Sv 128
#define Dv 300
#define VOC 20000
#define Kv 8
#define RROWS 4096      // B*S
#define G4 1200         // 4*D
#define ESTRIDE 20004   // padded row stride for logits/exp scratch
#define NC_LSTM 75      // persistent LSTM CTAs
#define SPLITK 5
#define KSPL 4000
#define VPART_LD 304

// ---------------- scratch (static device globals; no allocations) ------------
__device__ float g_X[RROWS * Dv];
__device__ float g_E[(size_t)RROWS * ESTRIDE];
__device__ float g_rowsum[RROWS];
__device__ float g_V[RROWS * Dv];
__device__ float g_XI[(size_t)RROWS * G4];
__device__ float g_CT[(size_t)Dv * ESTRIDE];            // [vocab;dembed]^T
__device__ float g_WihT[Dv * G4];                       // lstm_Wih^T
__device__ float g_Vpart[(size_t)SPLITK * RROWS * VPART_LD];
__device__ float g_hbuf[2][Bv * Dv];
__device__ float g_H[Bv * Kv * Dv];
__device__ unsigned g_bar;

__device__ __forceinline__ float sigmoidf_(float x) {
    return 1.0f / (1.0f + __expf(-x));
}

__device__ __forceinline__ float warp_dot300(const float* __restrict__ w,
                                             const float* hs, int lane) {
    float4 a0 = *(const float4*)(w + lane * 4);
    float4 b0 = *(const float4*)(hs + lane * 4);
    float s = a0.x * b0.x + a0.y * b0.y + a0.z * b0.z + a0.w * b0.w;
    float4 a1 = *(const float4*)(w + 128 + lane * 4);
    float4 b1 = *(const float4*)(hs + 128 + lane * 4);
    s += a1.x * b1.x + a1.y * b1.y + a1.z * b1.z + a1.w * b1.w;
    if (lane < 11) {
        float4 a2 = *(const float4*)(w + 256 + lane * 4);
        float4 b2 = *(const float4*)(hs + 256 + lane * 4);
        s += a2.x * b2.x + a2.y * b2.y + a2.z * b2.z + a2.w * b2.w;
    }
#pragma unroll
    for (int off = 16; off > 0; off >>= 1)
        s += __shfl_down_sync(0xffffffffu, s, off);
    return s;
}

// ---------------- bf16 split helpers -----------------------------------------
__device__ __forceinline__ void split2(float x0, float x1, unsigned& hi,
                                       unsigned& lo) {
    __nv_bfloat16 h0 = __float2bfloat16_rn(x0);
    __nv_bfloat16 h1 = __float2bfloat16_rn(x1);
    float r0 = x0 - __bfloat162float(h0);
    float r1 = x1 - __bfloat162float(h1);
    __nv_bfloat16 l0 = __float2bfloat16_rn(r0);
    __nv_bfloat16 l1 = __float2bfloat16_rn(r1);
    hi = ((unsigned)__bfloat16_as_ushort(h1) << 16) | __bfloat16_as_ushort(h0);
    lo = ((unsigned)__bfloat16_as_ushort(l1) << 16) | __bfloat16_as_ushort(l0);
}

__device__ __forceinline__ void mma16(float* c, const unsigned* a,
                                      const unsigned* b) {
    asm volatile(
        "mma.sync.aligned.m16n8k16.row.col.f32.bf16.bf16.f32 "
        "{%0,%1,%2,%3}, {%4,%5,%6,%7}, {%8,%9}, {%0,%1,%2,%3};\n"
        : "+f"(c[0]), "+f"(c[1]), "+f"(c[2]), "+f"(c[3])
        : "r"(a[0]), "r"(a[1]), "r"(a[2]), "r"(a[3]), "r"(b[0]), "r"(b[1]));
}

__device__ __forceinline__ float4 ld4g(const float* p, int v) {
    if (v >= 4) return *(const float4*)p;
    float4 r = make_float4(0.f, 0.f, 0.f, 0.f);
    if (v > 0) r.x = p[0];
    if (v > 1) r.y = p[1];
    if (v > 2) r.z = p[2];
    return r;
}

// ---------------- transpose --------------------------------------------------
__global__ void k_transpose(const float* __restrict__ src, int nrows, int ncols,
                            const float* __restrict__ alt, float* __restrict__ dst,
                            int ldd) {
    __shared__ float t[32][33];
    int n0 = blockIdx.x * 32, k0 = blockIdx.y * 32;
    int x = threadIdx.x, y = threadIdx.y;
    int ntot = nrows + (alt ? 1 : 0);
    for (int i = y; i < 32; i += 8) {
        int n = n0 + i, k = k0 + x;
        float v = 0.f;
        if (k < ncols) {
            if (n < nrows) v = src[(size_t)n * ncols + k];
            else if (alt != nullptr && n == nrows) v = alt[k];
        }
        t[i][x] = v;
    }
    __syncthreads();
    for (int i = y; i < 32; i += 8) {
        int k = k0 + i, n = n0 + x;
        if (k < ncols && n < ntot)
            dst[(size_t)k * ldd + n] = t[x][i];
    }
}

// ---------------- split-bf16 NN GEMM -----------------------------------------
// BM=128, BN=128, BK=32, 512 threads, 16 warps (4m x 4n), warp tile 32x32.
// 3-term split: Ahi*Bhi + Ahi*Blo + Alo*Bhi, fp32 accum.
// epi 0: plain (+ optional bias). epi 2: raw partial store (split-K),
//        C offset by blockIdx.z * partStride.
#define APITCH 20
#define ABUF 2560      // 128*20
#define BPITCH 136
#define BBUF 2176      // 16*136
#define MMA_SMEM 75776 // (2*2560*2 + 2*2176*2) * 4 bytes

__global__ __launch_bounds__(512) void mma_nn(
    const float* __restrict__ A, int lda,
    const float* __restrict__ Bt, int ldb,
    const float* __restrict__ bias,
    float* __restrict__ C, int ldc, int N, int K, int ksplit,
    size_t partStride, int epi) {
    extern __shared__ unsigned smu[];
    unsigned* Ahi = smu;                // [2][128][20]
    unsigned* Alo = smu + 2 * ABUF;
    unsigned* Bhi = smu + 4 * ABUF;     // [2][16][136]
    unsigned* Blo = smu + 4 * ABUF + 2 * BBUF;

    int tid = threadIdx.x;
    int m0 = blockIdx.x * 128, n0 = blockIdx.y * 128;
    int kbase = blockIdx.z * ksplit;
    int ksize = K - kbase;
    if (ksize > ksplit) ksize = ksplit;
    const float* Ap = A + kbase;
    const float* Bp = Bt + (size_t)kbase * ldb;

    int lane = tid & 31, w = tid >> 5;
    int wm = (w >> 2) * 32, wn = (w & 3) * 32;

    float c[2][4][4];
#pragma unroll
    for (int i = 0; i < 2; i++)
#pragma unroll
        for (int j = 0; j < 4; j++)
#pragma unroll
            for (int q = 0; q < 4; q++) c[i][j][q] = 0.f;

    // load mapping
    int am = tid >> 2, aq = tid & 3;        // A row, k-quarter (2 f4/thread)
    int bj = tid >> 5, bn4 = (tid & 31) * 4;  // B k2-pair row (2 f4/thread)

    const float* Arow = Ap + (size_t)(m0 + am) * lda;
    int vn = N - (n0 + bn4);

    float4 pa0, pa1, pb0, pb1;
    const int nIter = (ksize + 31) >> 5;

    // prologue (k0 = 0)
    {
        int kk0 = aq * 4, kk1 = 16 + aq * 4;
        pa0 = ld4g(Arow + kk0, ksize - kk0);
        pa1 = ld4g(Arow + kk1, ksize - kk1);
        int gk0 = 2 * bj, gk1 = gk0 + 1;
        pb0 = (gk0 < ksize) ? ld4g(Bp + (size_t)gk0 * ldb + n0 + bn4, vn)
                            : make_float4(0, 0, 0, 0);
        pb1 = (gk1 < ksize) ? ld4g(Bp + (size_t)gk1 * ldb + n0 + bn4, vn)
                            : make_float4(0, 0, 0, 0);
    }

    for (int it = 0; it < nIter; ++it) {
        int buf = it & 1;
        // store prefetched regs -> shared (split)
        {
            unsigned h0, h1, l0, l1;
            unsigned* dsthA = Ahi + buf * ABUF + am * APITCH;
            unsigned* dstlA = Alo + buf * ABUF + am * APITCH;
            split2(pa0.x, pa0.y, h0, l0);
            split2(pa0.z, pa0.w, h1, l1);
            *(uint2*)&dsthA[2 * aq] = make_uint2(h0, h1);
            *(uint2*)&dstlA[2 * aq] = make_uint2(l0, l1);
            split2(pa1.x, pa1.y, h0, l0);
            split2(pa1.z, pa1.w, h1, l1);
            *(uint2*)&dsthA[8 + 2 * aq] = make_uint2(h0, h1);
            *(uint2*)&dstlA[8 + 2 * aq] = make_uint2(l0, l1);

            unsigned bh[4], bl[4];
            split2(pb0.x, pb1.x, bh[0], bl[0]);
            split2(pb0.y, pb1.y, bh[1], bl[1]);
            split2(pb0.z, pb1.z, bh[2], bl[2]);
            split2(pb0.w, pb1.w, bh[3], bl[3]);
            *(uint4*)&Bhi[buf * BBUF + bj * BPITCH + bn4] =
                make_uint4(bh[0], bh[1], bh[2], bh[3]);
            *(uint4*)&Blo[buf * BBUF + bj * BPITCH + bn4] =
                make_uint4(bl[0], bl[1], bl[2], bl[3]);
        }
        __syncthreads();

        // next-stage global loads
        if (it + 1 < nIter) {
            int k0 = (it + 1) << 5;
            int kk0 = k0 + aq * 4, kk1 = k0 + 16 + aq * 4;
            pa0 = ld4g(Arow + kk0, ksize - kk0);
            pa1 = ld4g(Arow + kk1, ksize - kk1);
            int gk0 = k0 + 2 * bj, gk1 = gk0 + 1;
            pb0 = (gk0 < ksize) ? ld4g(Bp + (size_t)gk0 * ldb + n0 + bn4, vn)
                                : make_float4(0, 0, 0, 0);
            pb1 = (gk1 < ksize) ? ld4g(Bp + (size_t)gk1 * ldb + n0 + bn4, vn)
                                : make_float4(0, 0, 0, 0);
        }

        // compute: two k16 steps
        const unsigned* AhiB = Ahi + buf * ABUF;
        const unsigned* AloB = Alo + buf * ABUF;
        const unsigned* BhiB = Bhi + buf * BBUF;
        const unsigned* BloB = Blo + buf * BBUF;
#pragma unroll
        for (int s = 0; s < 2; s++) {
            int k2a = s * 8 + (lane & 3);
            unsigned ah[2][4], al[2][4];
#pragma unroll
            for (int mi = 0; mi < 2; mi++) {
                int r = wm + mi * 16 + (lane >> 2);
                ah[mi][0] = AhiB[r * APITCH + k2a];
                ah[mi][1] = AhiB[(r + 8) * APITCH + k2a];
                ah[mi][2] = AhiB[r * APITCH + k2a + 4];
                ah[mi][3] = AhiB[(r + 8) * APITCH + k2a + 4];
                al[mi][0] = AloB[r * APITCH + k2a];
                al[mi][1] = AloB[(r + 8) * APITCH + k2a];
                al[mi][2] = AloB[r * APITCH + k2a + 4];
                al[mi][3] = AloB[(r + 8) * APITCH + k2a + 4];
            }
#pragma unroll
            for (int nj = 0; nj < 4; nj++) {
                int nb = wn + nj * 8 + (lane >> 2);
                unsigned bh[2], bl[2];
                bh[0] = BhiB[k2a * BPITCH + nb];
                bh[1] = BhiB[(k2a + 4) * BPITCH + nb];
                bl[0] = BloB[k2a * BPITCH + nb];
                bl[1] = BloB[(k2a + 4) * BPITCH + nb];
#pragma unroll
                for (int mi = 0; mi < 2; mi++) {
                    mma16(c[mi][nj], ah[mi], bh);
                    mma16(c[mi][nj], ah[mi], bl);
                    mma16(c[mi][nj], al[mi], bh);
                }
            }
        }
        __syncthreads();
    }

    // epilogue
    float* Cp = C + blockIdx.z * partStride;
#pragma unroll
    for (int mi = 0; mi < 2; mi++) {
        int r1 = m0 + wm + mi * 16 + (lane >> 2);
        int r2 = r1 + 8;
#pragma unroll
        for (int nj = 0; nj < 4; nj++) {
            int col0 = n0 + wn + nj * 8 + (lane & 3) * 2;
#pragma unroll
            for (int q = 0; q < 2; q++) {
                int col = col0 + q;
                if (col < N) {
                    float v1 = c[mi][nj][q];
                    float v2 = c[mi][nj][2 + q];
                    if (epi == 0 && bias != nullptr) {
                        v1 += bias[col];
                        v2 += bias[col];
                    }
                    Cp[(size_t)r1 * ldc + col] = v1;
                    Cp[(size_t)r2 * ldc + col] = v2;
                }
            }
        }
    }
}

// ---------------- split-K reduce + V epilogue --------------------------------
__global__ void k_vreduce(const float* __restrict__ part,
                          const float* __restrict__ Emat,
                          const float* __restrict__ rowsum,
                          const float* __restrict__ words,
                          float* __restrict__ V) {
    int idx = blockIdx.x * 256 + threadIdx.x;
    if (idx >= RROWS * Dv) return;
    int r = idx / Dv, d = idx - r * Dv;
    float s = 0.f;
#pragma unroll
    for (int z = 0; z < SPLITK; z++)
        s += part[(size_t)z * RROWS * VPART_LD + (size_t)r * VPART_LD + d];
    float pl = Emat[(size_t)r * ESTRIDE + VOC];
    V[idx] = (s + pl * words[idx]) * (1.0f / rowsum[r]);
}

// ---------------- row softmax (vectorized) -----------------------------------
__global__ void k_softmax(float* __restrict__ E, float* __restrict__ rowsum) {
    int r = blockIdx.x;
    float* row = E + (size_t)r * ESTRIDE;
    float4* row4 = (float4*)row;
    int tid = threadIdx.x;  // 256
    __shared__ float red[256];
    float m = -1e30f;
    for (int v = tid; v < 5000; v += 256) {
        float4 f = row4[v];
        m = fmaxf(m, fmaxf(fmaxf(f.x, f.y), fmaxf(f.z, f.w)));
    }
    if (tid == 0) m = fmaxf(m, row[VOC]);
    red[tid] = m;
    __syncthreads();
    for (int s = 128; s > 0; s >>= 1) {
        if (tid < s) red[tid] = fmaxf(red[tid], red[tid + s]);
        __syncthreads();
    }
    m = red[0];
    __syncthreads();
    float sum = 0.f;
    for (int v = tid; v < 5000; v += 256) {
        float4 f = row4[v];
        f.x = __expf(f.x - m);
        f.y = __expf(f.y - m);
        f.z = __expf(f.z - m);
        f.w = __expf(f.w - m);
        row4[v] = f;
        sum += f.x + f.y + f.z + f.w;
    }
    if (tid == 0) {
        float e = __expf(row[VOC] - m);
        row[VOC] = e;
        sum += e;
    }
    red[tid] = sum;
    __syncthreads();
    for (int s = 128; s > 0; s >>= 1) {
        if (tid < s) red[tid] += red[tid + s];
        __syncthreads();
    }
    if (tid == 0) rowsum[r] = red[0];
}

// ---------------- init for LSTM ----------------------------------------------
__global__ void k_init() {
    int i = blockIdx.x * blockDim.x + threadIdx.x;
    if (i < Bv * Dv) g_hbuf[0][i] = 0.f;
    if (i == 0) g_bar = 0u;
}

// ---------------- persistent LSTM --------------------------------------------
__global__ __launch_bounds__(256) void k_lstm(const float* __restrict__ XI,
                                              const float* __restrict__ Whh,
                                              const float* __restrict__ bhh,
                                              const int* __restrict__ lengths) {
    extern __shared__ float sm[];
    float* Wsh = sm;                     // 16*300
    float* hsh = Wsh + 16 * 300;         // 32*300
    float* gsh = hsh + 32 * 300;         // 32*16
    float* csh = gsh + 32 * 16;          // 32*4
    float* bsh = csh + 32 * 4;           // 16
    int* lsh = (int*)(bsh + 16);         // 32

    int tid = threadIdx.x;
    int d0 = blockIdx.x * 4;
    int lane = tid & 31, w = tid >> 5;

    for (int i = tid; i < 16 * 300; i += 256) {
        int r = i / 300, cc = i - r * 300;
        Wsh[i] = Whh[(size_t)((r >> 2) * 300 + d0 + (r & 3)) * 300 + cc];
    }
    if (tid < 16) bsh[tid] = bhh[(tid >> 2) * 300 + d0 + (tid & 3)];
    if (tid < 32) lsh[tid] = lengths[tid];
    for (int i = tid; i < 128; i += 256) csh[i] = 0.f;
    __syncthreads();

    volatile unsigned* barp = &g_bar;

    for (int t = 0; t < Sv; ++t) {
        const float* hin = g_hbuf[t & 1];
        float* hout = g_hbuf[(t + 1) & 1];
        for (int i = tid; i < (32 * 300) / 4; i += 256)
            ((float4*)hsh)[i] = ((const float4*)hin)[i];
        for (int i = tid; i < 512; i += 256) {
            int b = i >> 4, r = i & 15;
            gsh[i] = XI[(size_t)((b << 7) + t) * G4 + (r >> 2) * 300 + d0 + (r & 3)] +
                     bsh[r];
        }
        __syncthreads();
        for (int i = w; i < 512; i += 8) {
            int b = i >> 4, r = i & 15;
            float s = warp_dot300(Wsh + r * 300, hsh + b * 300, lane);
            if (lane == 0) gsh[i] += s;
        }
        __syncthreads();
        if (tid < 128) {
            int b = tid >> 2, j = tid & 3;
            float hnew;
            if (t < lsh[b]) {
                float gi = sigmoidf_(gsh[b * 16 + j]);
                float gf = sigmoidf_(gsh[b * 16 + 4 + j]);
                float gg = tanhf(gsh[b * 16 + 8 + j]);
                float go = sigmoidf_(gsh[b * 16 + 12 + j]);
                float cn = gf * csh[tid] + gi * gg;
                csh[tid] = cn;
                hnew = go * tanhf(cn);
            } else {
                hnew = hsh[b * 300 + d0 + j];
            }
            hout[b * 300 + d0 + j] = hnew;
        }
        __threadfence();
        __syncthreads();
        if (tid == 0) {
            atomicAdd((unsigned*)&g_bar, 1u);
            unsigned target = (unsigned)(t + 1) * NC_LSTM;
            while (*barp < target) {
            }
            __threadfence();
        }
        __syncthreads();
    }
}

// ---------------- RNN readout -------------------------------------------------
__global__ void k_rnn(const float* __restrict__ q, const float* __restrict__ Wih,
                      const float* __restrict__ Whh, const float* __restrict__ bih,
                      const float* __restrict__ bhh, float* __restrict__ H) {
    int b = blockIdx.x;
    int tid = threadIdx.x;  // 320
    int warp = tid >> 5, lane = tid & 31;
    __shared__ __align__(16) float qs[Dv];
    __shared__ __align__(16) float hs[Dv];
    __shared__ float A[Dv];
    __shared__ float hn[Dv];
    for (int i = tid; i < Dv; i += 320) {
        qs[i] = q[b * Dv + i];
        hs[i] = 0.f;
    }
    __syncthreads();
    for (int r = warp; r < Dv; r += 10) {
        float s = warp_dot300(Wih + (size_t)r * Dv, qs, lane);
        if (lane == 0) A[r] = s + bih[r] + bhh[r];
    }
    __syncthreads();
    for (int k = 0; k < Kv; k++) {
        for (int r = warp; r < Dv; r += 10) {
            float s = warp_dot300(Whh + (size_t)r * Dv, hs, lane);
            if (lane == 0) hn[r] = tanhf(A[r] + s);
        }
        __syncthreads();
        for (int i = tid; i < Dv; i += 320) {
            float v = hn[i];
            hs[i] = v;
            H[(size_t)b * Kv * Dv + k * Dv + i] = v;
        }
        __syncthreads();
    }
}

// ---------------- attention ---------------------------------------------------
__global__ void k_attn(const float* __restrict__ H, const float* __restrict__ V,
                       const int* __restrict__ lengths, float* __restrict__ R) {
    int kk = blockIdx.x, b = blockIdx.y;
    int tid = threadIdx.x;  // 128
    __shared__ __align__(16) float Hs[Dv];
    __shared__ float rbuf[128];
    __shared__ float p[128];
    for (int i = tid; i < Dv; i += 128)
        Hs[i] = H[(size_t)b * Kv * Dv + kk * Dv + i];
    __syncthreads();
    int len = lengths[b];
    float sc = -1e30f;
    if (tid < len) {
        const float* vrow = V + (size_t)(b * Sv + tid) * Dv;
        float s = 0.f;
        for (int d = 0; d < Dv; d += 4) {
            float4 v4 = *(const float4*)&vrow[d];
            s += v4.x * Hs[d] + v4.y * Hs[d + 1] + v4.z * Hs[d + 2] + v4.w * Hs[d + 3];
        }
        sc = s;
    }
    rbuf[tid] = sc;
    __syncthreads();
    for (int s = 64; s > 0; s >>= 1) {
        if (tid < s) rbuf[tid] = fmaxf(rbuf[tid], rbuf[tid + s]);
        __syncthreads();
    }
    float m = rbuf[0];
    __syncthreads();
    float e = (tid < len) ? __expf(sc - m) : 0.f;
    rbuf[tid] = e;
    __syncthreads();
    for (int s = 64; s > 0; s >>= 1) {
        if (tid < s) rbuf[tid] += rbuf[tid + s];
        __syncthreads();
    }
    float denom = rbuf[0];
    __syncthreads();
    p[tid] = e / denom;
    __syncthreads();
    float* out = R + (size_t)(b * Kv + kk) * Dv;
    for (int d = tid; d < Dv; d += 128) {
        float s = 0.f;
        for (int si = 0; si < Sv; si++)
            s += p[si] * V[(size_t)(b * Sv + si) * Dv + d];
        out[d] = s;
    }
}

// ---------------- launch ------------------------------------------------------
extern "C" void kernel_launch(void* const* d_in, const int* in_sizes, int n_in,
                              void* d_out, int out_size) {
    const float* words    = (const float*)d_in[0];
    const int*   lengths  = (const int*)d_in[1];
    const float* vocab    = (const float*)d_in[2];
    const float* dembed   = (const float*)d_in[3];
    const float* W        = (const float*)d_in[4];
    const float* lstm_Wih = (const float*)d_in[5];
    const float* lstm_Whh = (const float*)d_in[6];
    const float* lstm_bih = (const float*)d_in[7];
    const float* lstm_bhh = (const float*)d_in[8];
    const float* rnn_Wih  = (const float*)d_in[9];
    const float* rnn_Whh  = (const float*)d_in[10];
    const float* rnn_bih  = (const float*)d_in[11];
    const float* rnn_bhh  = (const float*)d_in[12];
    float* out = (float*)d_out;

    float *pX, *pE, *pRS, *pV, *pXI, *pCT, *pWT, *pVP, *pH, *pHB;
    cudaGetSymbolAddress((void**)&pX, g_X);
    cudaGetSymbolAddress((void**)&pE, g_E);
    cudaGetSymbolAddress((void**)&pRS, g_rowsum);
    cudaGetSymbolAddress((void**)&pV, g_V);
    cudaGetSymbolAddress((void**)&pXI, g_XI);
    cudaGetSymbolAddress((void**)&pCT, g_CT);
    cudaGetSymbolAddress((void**)&pWT, g_WihT);
    cudaGetSymbolAddress((void**)&pVP, g_Vpart);
    cudaGetSymbolAddress((void**)&pH, g_H);
    cudaGetSymbolAddress((void**)&pHB, g_hbuf);

    cudaFuncSetAttribute(mma_nn, cudaFuncAttributeMaxDynamicSharedMemorySize,
                         MMA_SMEM);
    cudaFuncSetAttribute(k_lstm, cudaFuncAttributeMaxDynamicSharedMemorySize,
                         61440);

    // 0) transposes: CT = [vocab; dembed]^T, WihT = lstm_Wih^T
    k_transpose<<<dim3((VOC + 1 + 31) / 32, (Dv + 31) / 32), dim3(32, 8)>>>(
        vocab, VOC, Dv, dembed, pCT, ESTRIDE);
    k_transpose<<<dim3((G4 + 31) / 32, (Dv + 31) / 32), dim3(32, 8)>>>(
        lstm_Wih, G4, Dv, nullptr, pWT, G4);

    // 1) X = words @ W
    mma_nn<<<dim3(RROWS / 128, (Dv + 127) / 128, 1), 512, MMA_SMEM>>>(
        words, Dv, W, Dv, nullptr, pX, Dv, Dv, Dv, Dv, 0, 0);

    // 2) logits = X @ CT -> g_E (N=20001)
    mma_nn<<<dim3(RROWS / 128, (VOC + 1 + 127) / 128, 1), 512, MMA_SMEM>>>(
        pX, Dv, pCT, ESTRIDE, nullptr, pE, ESTRIDE, VOC + 1, Dv, Dv, 0, 0);

    // 3) row softmax (unnormalized exp + rowsum)
    k_softmax<<<RROWS, 256>>>(pE, pRS);

    // 4) V partials = E @ vocab (split-K over 5), then reduce + epilogue
    mma_nn<<<dim3(RROWS / 128, (Dv + 127) / 128, SPLITK), 512, MMA_SMEM>>>(
        pE, ESTRIDE, vocab, Dv, nullptr, pVP, VPART_LD, Dv, VOC, KSPL,
        (size_t)RROWS * VPART_LD, 2);
    k_vreduce<<<(RROWS * Dv + 255) / 256, 256>>>(pVP, pE, pRS, words, pV);

    // 5) XI = V @ WihT + bih (N=1200)
    mma_nn<<<dim3(RROWS / 128, (G4 + 127) / 128, 1), 512, MMA_SMEM>>>(
        pV, Dv, pWT, G4, lstm_bih, pXI, G4, G4, Dv, Dv, 0, 0);

    // 6) persistent LSTM
    k_init<<<(Bv * Dv + 255) / 256, 256>>>();
    k_lstm<<<NC_LSTM, 256, 61440>>>(pXI, lstm_Whh, lstm_bhh, lengths);

    // 7) RNN readout
    k_rnn<<<Bv, 320>>>(pHB, rnn_Wih, rnn_Whh, rnn_bih, rnn_bhh, pH);

    // 8) attention -> output
    k_attn<<<dim3(Kv, Bv), 128>>>(pH, pV, lengths, out);
}

// round 5
// speedup vs baseline: 2.9062x; 1.5924x over previous
#include <cuda_runtime.h>
#include <cuda_bf16.h>
#include <math.h>

#define Bv 32
#define Sv 128
#define Dv 300
#define VOC 20000
#define Kv 8
#define RROWS 4096
#define G4 1200
#define ESTRIDE 20004
#define NC_LSTM 75
#define SPLITK 5
#define KSPL2 2000          // k2 (pairs) per split for V GEMM
#define VPART_LD 304

// ---------------- scratch (static device globals; zero-initialized) ----------
__device__ float g_E[(size_t)RROWS * ESTRIDE];          // fp32 logits
__device__ float g_rowsum[RROWS];
__device__ float g_pl[RROWS];
__device__ float g_V[RROWS * Dv];
__device__ float g_Vpart[(size_t)SPLITK * RROWS * VPART_LD];
__device__ float g_XIT[(size_t)Sv * G4 * Bv];           // [t][1200][32]
__device__ float g_hT[2][Dv * Bv];                      // [d][b]
__device__ float g_H[Bv * Kv * Dv];
__device__ unsigned g_bar;

// split-bf16 packed operands (hi/lo), k-pairs as 32-bit words
__device__ unsigned g_wordsH[RROWS * 160], g_wordsL[RROWS * 160];
__device__ unsigned g_WH[160 * 304], g_WL[160 * 304];
__device__ unsigned g_XH[RROWS * 160], g_XL[RROWS * 160];
__device__ unsigned g_CTH[(size_t)160 * ESTRIDE], g_CTL[(size_t)160 * ESTRIDE];
__device__ unsigned g_EH[(size_t)RROWS * 10000], g_EL[(size_t)RROWS * 10000];
__device__ unsigned g_vocH[10000 * 304], g_vocL[10000 * 304];
__device__ unsigned g_VH[RROWS * 160], g_VL[RROWS * 160];
__device__ unsigned g_WihTH[160 * 1204], g_WihTL[160 * 1204];

__device__ __forceinline__ float sigmoidf_(float x) {
    return 1.0f / (1.0f + __expf(-x));
}

__device__ __forceinline__ void split2(float x0, float x1, unsigned& hi,
                                       unsigned& lo) {
    __nv_bfloat16 h0 = __float2bfloat16_rn(x0);
    __nv_bfloat16 h1 = __float2bfloat16_rn(x1);
    float r0 = x0 - __bfloat162float(h0);
    float r1 = x1 - __bfloat162float(h1);
    __nv_bfloat16 l0 = __float2bfloat16_rn(r0);
    __nv_bfloat16 l1 = __float2bfloat16_rn(r1);
    hi = ((unsigned)__bfloat16_as_ushort(h1) << 16) | __bfloat16_as_ushort(h0);
    lo = ((unsigned)__bfloat16_as_ushort(l1) << 16) | __bfloat16_as_ushort(l0);
}

__device__ __forceinline__ void mma16(float* c, const unsigned* a,
                                      const unsigned* b) {
    asm volatile(
        "mma.sync.aligned.m16n8k16.row.col.f32.bf16.bf16.f32 "
        "{%0,%1,%2,%3}, {%4,%5,%6,%7}, {%8,%9}, {%0,%1,%2,%3};\n"
        : "+f"(c[0]), "+f"(c[1]), "+f"(c[2]), "+f"(c[3])
        : "r"(a[0]), "r"(a[1]), "r"(a[2]), "r"(a[3]), "r"(b[0]), "r"(b[1]));
}

__device__ __forceinline__ void cpa16(unsigned* dst, const unsigned* src,
                                      int bytes) {
    unsigned d = (unsigned)__cvta_generic_to_shared(dst);
    asm volatile("cp.async.cg.shared.global [%0], [%1], 16, %2;\n" ::"r"(d),
                 "l"(src), "r"(bytes));
}
__device__ __forceinline__ void cpa_commit() {
    asm volatile("cp.async.commit_group;\n");
}
__device__ __forceinline__ void cpa_wait1() {
    asm volatile("cp.async.wait_group 1;\n");
}

// ---------------- prepass: split A-style (src [M][K] -> hi/lo [M][lda2]) -----
__global__ void k_splitA(const float* __restrict__ src, int M, int K,
                         unsigned* __restrict__ hi, unsigned* __restrict__ lo,
                         int lda2) {
    int idx = blockIdx.x * 256 + threadIdx.x;
    int K2 = K >> 1;
    if (idx >= M * K2) return;
    int m = idx / K2, j = idx - m * K2;
    float2 v = *(const float2*)&src[(size_t)m * K + 2 * j];
    unsigned h, l;
    split2(v.x, v.y, h, l);
    hi[(size_t)m * lda2 + j] = h;
    lo[(size_t)m * lda2 + j] = l;
}

// ---------------- prepass: src already [K][N]; pack pairs across k -----------
__global__ void k_splitB_N(const float* __restrict__ src, int K, int N,
                           unsigned* __restrict__ hi, unsigned* __restrict__ lo,
                           int ldo) {
    int idx = blockIdx.x * 256 + threadIdx.x;
    int K2 = K >> 1;
    if (idx >= K2 * N) return;
    int k2 = idx / N, n = idx - k2 * N;
    float a = src[(size_t)(2 * k2) * N + n];
    float b = src[(size_t)(2 * k2 + 1) * N + n];
    unsigned h, l;
    split2(a, b, h, l);
    hi[(size_t)k2 * ldo + n] = h;
    lo[(size_t)k2 * ldo + n] = l;
}

// ---------------- prepass: src [Nsrc][K] row-major; out = src^T split --------
__global__ void k_splitB_T(const float* __restrict__ src, int Nsrc, int K,
                           const float* __restrict__ alt,
                           unsigned* __restrict__ hi, unsigned* __restrict__ lo,
                           int ldo) {
    __shared__ float tile[32][33];
    int n0 = blockIdx.x * 32, k0 = blockIdx.y * 32;
    int x = threadIdx.x, y = threadIdx.y;  // 32x8
    int Ntot = Nsrc + (alt ? 1 : 0);
    for (int i = y; i < 32; i += 8) {
        int n = n0 + i, k = k0 + x;
        float v = 0.f;
        if (k < K) {
            if (n < Nsrc) v = src[(size_t)n * K + k];
            else if (alt != nullptr && n == Nsrc) v = alt[k];
        }
        tile[i][x] = v;
    }
    __syncthreads();
    for (int i = y; i < 16; i += 8) {
        int k2 = (k0 >> 1) + i;
        int n = n0 + x;
        if (n < Ntot) {
            unsigned h, l;
            split2(tile[x][2 * i], tile[x][2 * i + 1], h, l);
            hi[(size_t)k2 * ldo + n] = h;
            lo[(size_t)k2 * ldo + n] = l;
        }
    }
}

// ---------------- split-bf16 NN GEMM, cp.async 3-stage -----------------------
// BM=128, BN=128, BK=32 (16 k-pairs), 512 threads, 16 warps (4m x 4n).
// epi 0: fp32 C (+bias). epi 2: fp32 partial at z*partStride.
// epi 3: split-pack write to Ch/Cl. epi 4: bias + XIT scatter.
#define APITCH 20
#define ABUFW 2560
#define BPITCH 132
#define BBUFW 2112
#define STGW 9344
#define MMA_SMEM (3 * STGW * 4)

__global__ __launch_bounds__(512) void mma_nn(
    const unsigned* __restrict__ Agh, const unsigned* __restrict__ Agl, int lda2,
    const unsigned* __restrict__ Bgh, const unsigned* __restrict__ Bgl, int ldb,
    const float* __restrict__ bias, float* __restrict__ C, int ldc,
    unsigned* __restrict__ Ch, unsigned* __restrict__ Cl, int ldc2,
    int N, int ksplit2, int K2, size_t partStride, int epi) {
    extern __shared__ unsigned smem[];
    int tid = threadIdx.x;
    int m0 = blockIdx.x * 128, n0 = blockIdx.y * 128;
    int kb2 = blockIdx.z * ksplit2;
    int ks2 = K2 - kb2;
    if (ks2 > ksplit2) ks2 = ksplit2;
    int nIter = (ks2 + 15) >> 4;

    int lane = tid & 31, w = tid >> 5;
    int wm = (w >> 2) * 32, wn = (w & 3) * 32;

    // load mapping
    int am = tid >> 2, ac = tid & 3;
    int bk = tid >> 5, bc = tid & 31;
    int c0b = n0 + bc * 4;
    int validb = N - c0b;
    int bbytes = validb >= 4 ? 16 : (validb > 0 ? validb * 4 : 0);
    int ccb = (bbytes > 0) ? c0b : 0;

    float c[2][4][4];
#pragma unroll
    for (int i = 0; i < 2; i++)
#pragma unroll
        for (int j = 0; j < 4; j++)
#pragma unroll
            for (int q = 0; q < 4; q++) c[i][j][q] = 0.f;

    // prologue: issue stages 0 and 1
#pragma unroll
    for (int p = 0; p < 2; p++) {
        if (p < nIter) {
            unsigned* sb = smem + p * STGW;
            size_t aidx = (size_t)(m0 + am) * lda2 + kb2 + (p << 4) + ac * 4;
            cpa16(&sb[am * APITCH + ac * 4], Agh + aidx, 16);
            cpa16(&sb[ABUFW + am * APITCH + ac * 4], Agl + aidx, 16);
            size_t bidx = (size_t)(kb2 + (p << 4) + bk) * ldb + ccb;
            cpa16(&sb[2 * ABUFW + bk * BPITCH + bc * 4], Bgh + bidx, bbytes);
            cpa16(&sb[2 * ABUFW + BBUFW + bk * BPITCH + bc * 4], Bgl + bidx,
                  bbytes);
        }
        cpa_commit();
    }

    for (int it = 0; it < nIter; ++it) {
        cpa_wait1();
        __syncthreads();
        unsigned* sb = smem + (it % 3) * STGW;
        const unsigned* AhiB = sb;
        const unsigned* AloB = sb + ABUFW;
        const unsigned* BhiB = sb + 2 * ABUFW;
        const unsigned* BloB = sb + 2 * ABUFW + BBUFW;

#pragma unroll
        for (int s = 0; s < 2; s++) {
            int k2a = s * 8 + (lane & 3);
            unsigned ah[2][4], al[2][4];
#pragma unroll
            for (int mi = 0; mi < 2; mi++) {
                int r = wm + mi * 16 + (lane >> 2);
                ah[mi][0] = AhiB[r * APITCH + k2a];
                ah[mi][1] = AhiB[(r + 8) * APITCH + k2a];
                ah[mi][2] = AhiB[r * APITCH + k2a + 4];
                ah[mi][3] = AhiB[(r + 8) * APITCH + k2a + 4];
                al[mi][0] = AloB[r * APITCH + k2a];
                al[mi][1] = AloB[(r + 8) * APITCH + k2a];
                al[mi][2] = AloB[r * APITCH + k2a + 4];
                al[mi][3] = AloB[(r + 8) * APITCH + k2a + 4];
            }
#pragma unroll
            for (int nj = 0; nj < 4; nj++) {
                int nb = wn + nj * 8 + (lane >> 2);
                unsigned bh[2], bl[2];
                bh[0] = BhiB[k2a * BPITCH + nb];
                bh[1] = BhiB[(k2a + 4) * BPITCH + nb];
                bl[0] = BloB[k2a * BPITCH + nb];
                bl[1] = BloB[(k2a + 4) * BPITCH + nb];
#pragma unroll
                for (int mi = 0; mi < 2; mi++) {
                    mma16(c[mi][nj], ah[mi], bh);
                    mma16(c[mi][nj], ah[mi], bl);
                    mma16(c[mi][nj], al[mi], bh);
                }
            }
        }

        // issue loads for stage it+2
        if (it + 2 < nIter) {
            unsigned* sb2 = smem + ((it + 2) % 3) * STGW;
            int k2base = (it + 2) << 4;
            size_t aidx = (size_t)(m0 + am) * lda2 + kb2 + k2base + ac * 4;
            cpa16(&sb2[am * APITCH + ac * 4], Agh + aidx, 16);
            cpa16(&sb2[ABUFW + am * APITCH + ac * 4], Agl + aidx, 16);
            size_t bidx = (size_t)(kb2 + k2base + bk) * ldb + ccb;
            cpa16(&sb2[2 * ABUFW + bk * BPITCH + bc * 4], Bgh + bidx, bbytes);
            cpa16(&sb2[2 * ABUFW + BBUFW + bk * BPITCH + bc * 4], Bgl + bidx,
                  bbytes);
        }
        cpa_commit();
    }

    // ---- epilogue ----
#pragma unroll
    for (int mi = 0; mi < 2; mi++) {
        int r1 = m0 + wm + mi * 16 + (lane >> 2);
        int r2 = r1 + 8;
#pragma unroll
        for (int nj = 0; nj < 4; nj++) {
            int col0 = n0 + wn + nj * 8 + (lane & 3) * 2;
            if (epi == 3) {
                if (col0 + 1 < N) {
                    unsigned h, l;
                    split2(c[mi][nj][0], c[mi][nj][1], h, l);
                    Ch[(size_t)r1 * ldc2 + (col0 >> 1)] = h;
                    Cl[(size_t)r1 * ldc2 + (col0 >> 1)] = l;
                    split2(c[mi][nj][2], c[mi][nj][3], h, l);
                    Ch[(size_t)r2 * ldc2 + (col0 >> 1)] = h;
                    Cl[(size_t)r2 * ldc2 + (col0 >> 1)] = l;
                }
            } else if (epi == 4) {
#pragma unroll
                for (int q = 0; q < 2; q++) {
                    int col = col0 + q;
                    if (col < N) {
                        float b = bias[col];
                        C[((size_t)(r1 & 127) * G4 + col) * 32 + (r1 >> 7)] =
                            c[mi][nj][q] + b;
                        C[((size_t)(r2 & 127) * G4 + col) * 32 + (r2 >> 7)] =
                            c[mi][nj][2 + q] + b;
                    }
                }
            } else {
                float* Cp = C + blockIdx.z * partStride;
#pragma unroll
                for (int q = 0; q < 2; q++) {
                    int col = col0 + q;
                    if (col < N) {
                        float v1 = c[mi][nj][q];
                        float v2 = c[mi][nj][2 + q];
                        if (epi == 0 && bias != nullptr) {
                            v1 += bias[col];
                            v2 += bias[col];
                        }
                        Cp[(size_t)r1 * ldc + col] = v1;
                        Cp[(size_t)r2 * ldc + col] = v2;
                    }
                }
            }
        }
    }
}

// ---------------- softmax: fp32 logits -> split-bf16 exp packs ---------------
__global__ void k_softmax(const float* __restrict__ E, unsigned* __restrict__ EH,
                          unsigned* __restrict__ EL, float* __restrict__ pl,
                          float* __restrict__ rowsum) {
    int r = blockIdx.x;
    const float2* row2 = (const float2*)(E + (size_t)r * ESTRIDE);
    int tid = threadIdx.x;  // 256
    __shared__ float red[256];
    float m = -1e30f;
    for (int j = tid; j < 10000; j += 256) {
        float2 f = row2[j];
        m = fmaxf(m, fmaxf(f.x, f.y));
    }
    if (tid == 0) m = fmaxf(m, E[(size_t)r * ESTRIDE + VOC]);
    red[tid] = m;
    __syncthreads();
    for (int s = 128; s > 0; s >>= 1) {
        if (tid < s) red[tid] = fmaxf(red[tid], red[tid + s]);
        __syncthreads();
    }
    m = red[0];
    __syncthreads();
    float sum = 0.f;
    for (int j = tid; j < 10000; j += 256) {
        float2 f = row2[j];
        float e0 = __expf(f.x - m);
        float e1 = __expf(f.y - m);
        sum += e0 + e1;
        unsigned h, l;
        split2(e0, e1, h, l);
        EH[(size_t)r * 10000 + j] = h;
        EL[(size_t)r * 10000 + j] = l;
    }
    if (tid == 0) {
        float e = __expf(E[(size_t)r * ESTRIDE + VOC] - m);
        pl[r] = e;
        sum += e;
    }
    red[tid] = sum;
    __syncthreads();
    for (int s = 128; s > 0; s >>= 1) {
        if (tid < s) red[tid] += red[tid + s];
        __syncthreads();
    }
    if (tid == 0) rowsum[r] = red[0];
}

// ---------------- split-K reduce + V epilogue + V split ----------------------
__global__ void k_vreduce(const float* __restrict__ part,
                          const float* __restrict__ pl,
                          const float* __restrict__ rowsum,
                          const float* __restrict__ words,
                          float* __restrict__ V, unsigned* __restrict__ VH,
                          unsigned* __restrict__ VL) {
    int idx = blockIdx.x * 256 + threadIdx.x;
    if (idx >= RROWS * 150) return;
    int r = idx / 150, j = idx - r * 150;
    int d0 = 2 * j;
    float s0 = 0.f, s1 = 0.f;
#pragma unroll
    for (int z = 0; z < SPLITK; z++) {
        const float* p = part + (size_t)z * RROWS * VPART_LD +
                         (size_t)r * VPART_LD + d0;
        s0 += p[0];
        s1 += p[1];
    }
    float p_l = pl[r];
    float inv = 1.0f / rowsum[r];
    float v0 = (s0 + p_l * words[(size_t)r * Dv + d0]) * inv;
    float v1 = (s1 + p_l * words[(size_t)r * Dv + d0 + 1]) * inv;
    V[(size_t)r * Dv + d0] = v0;
    V[(size_t)r * Dv + d0 + 1] = v1;
    unsigned h, l;
    split2(v0, v1, h, l);
    VH[(size_t)r * 160 + j] = h;
    VL[(size_t)r * 160 + j] = l;
}

// ---------------- init for LSTM ----------------------------------------------
__global__ void k_init() {
    int i = blockIdx.x * blockDim.x + threadIdx.x;
    if (i < Dv * Bv) g_hT[0][i] = 0.f;
    if (i == 0) g_bar = 0u;
}

// ---------------- persistent LSTM (lane = batch) ------------------------------
// 75 CTAs; CTA owns d-slice [4*blk, +4) -> 16 gate rows. hT[d][b], XIT[t][r][b].
// Warp w: gate g = w&3 (4 rows), d-half = w>>2. c-state in registers.
__global__ __launch_bounds__(256) void k_lstm(const float* __restrict__ XIT,
                                              const float* __restrict__ Whh,
                                              const float* __restrict__ bhh,
                                              const int* __restrict__ lengths) {
    extern __shared__ float sm[];
    float* Wsh = sm;              // [16][300]
    float* hTs = Wsh + 4800;      // [300][32]
    float* psum = hTs + 9600;     // [2][16][32]
    float* bsh = psum + 1024;     // [16]
    int* lsh = (int*)(bsh + 16);  // [32]

    int tid = threadIdx.x, lane = tid & 31, w = tid >> 5;
    int d0 = blockIdx.x * 4;
    int half = w >> 2;
    int rg = (w & 3) * 4;

    for (int i = tid; i < 4800; i += 256) {
        int row = i / 300, d = i - row * 300;
        int g = row >> 2, j = row & 3;
        Wsh[i] = Whh[(size_t)(g * 300 + d0 + j) * 300 + d];
    }
    if (tid < 16) bsh[tid] = bhh[(tid >> 2) * 300 + d0 + (tid & 3)];
    if (tid < 32) lsh[tid] = lengths[tid];
    __syncthreads();

    float creg = 0.f;
    int bb = tid & 31, jj = (tid >> 5) & 3;
    volatile unsigned* barp = &g_bar;
    const float* W0 = Wsh + (rg + 0) * 300;
    const float* W1 = Wsh + (rg + 1) * 300;
    const float* W2 = Wsh + (rg + 2) * 300;
    const float* W3 = Wsh + (rg + 3) * 300;
    int dbeg = half * 150;

    for (int t = 0; t < Sv; ++t) {
        const float* hin = g_hT[t & 1];
        float* hout = g_hT[(t + 1) & 1];
        for (int i = tid; i < 2400; i += 256)
            ((float4*)hTs)[i] = ((const float4*)hin)[i];
        __syncthreads();

        {
            float a0 = 0.f, a1 = 0.f, a2 = 0.f, a3 = 0.f;
#pragma unroll 5
            for (int dd = 0; dd < 150; dd += 2) {
                int d = dbeg + dd;
                float hv0 = hTs[d * 32 + lane];
                float hv1 = hTs[(d + 1) * 32 + lane];
                float2 w0 = *(const float2*)(W0 + d);
                float2 w1 = *(const float2*)(W1 + d);
                float2 w2 = *(const float2*)(W2 + d);
                float2 w3 = *(const float2*)(W3 + d);
                a0 += w0.x * hv0 + w0.y * hv1;
                a1 += w1.x * hv0 + w1.y * hv1;
                a2 += w2.x * hv0 + w2.y * hv1;
                a3 += w3.x * hv0 + w3.y * hv1;
            }
            psum[half * 512 + (rg + 0) * 32 + lane] = a0;
            psum[half * 512 + (rg + 1) * 32 + lane] = a1;
            psum[half * 512 + (rg + 2) * 32 + lane] = a2;
            psum[half * 512 + (rg + 3) * 32 + lane] = a3;
        }
        __syncthreads();

        if (tid < 128) {
            float gv[4];
#pragma unroll
            for (int g = 0; g < 4; g++) {
                int row = g * 4 + jj;
                gv[g] = XIT[((size_t)t * G4 + g * 300 + d0 + jj) * 32 + bb] +
                        bsh[row] + psum[row * 32 + bb] + psum[512 + row * 32 + bb];
            }
            float hnew;
            if (t < lsh[bb]) {
                float gi = sigmoidf_(gv[0]);
                float gf = sigmoidf_(gv[1]);
                float gg = tanhf(gv[2]);
                float go = sigmoidf_(gv[3]);
                creg = gf * creg + gi * gg;
                hnew = go * tanhf(creg);
            } else {
                hnew = hTs[(d0 + jj) * 32 + bb];
            }
            hout[(d0 + jj) * 32 + bb] = hnew;
        }
        __threadfence();
        __syncthreads();
        if (tid == 0) {
            atomicAdd((unsigned*)&g_bar, 1u);
            unsigned target = (unsigned)(t + 1) * NC_LSTM;
            while (*barp < target) {
            }
            __threadfence();
        }
        __syncthreads();
    }
}

// ---------------- RNN readout (q from transposed hT) -------------------------
__device__ __forceinline__ float warp_dot300(const float* __restrict__ wv,
                                             const float* hs, int lane) {
    float4 a0 = *(const float4*)(wv + lane * 4);
    float4 b0 = *(const float4*)(hs + lane * 4);
    float s = a0.x * b0.x + a0.y * b0.y + a0.z * b0.z + a0.w * b0.w;
    float4 a1 = *(const float4*)(wv + 128 + lane * 4);
    float4 b1 = *(const float4*)(hs + 128 + lane * 4);
    s += a1.x * b1.x + a1.y * b1.y + a1.z * b1.z + a1.w * b1.w;
    if (lane < 11) {
        float4 a2 = *(const float4*)(wv + 256 + lane * 4);
        float4 b2 = *(const float4*)(hs + 256 + lane * 4);
        s += a2.x * b2.x + a2.y * b2.y + a2.z * b2.z + a2.w * b2.w;
    }
#pragma unroll
    for (int off = 16; off > 0; off >>= 1)
        s += __shfl_down_sync(0xffffffffu, s, off);
    return s;
}

__global__ void k_rnn(const float* __restrict__ qT, const float* __restrict__ Wih,
                      const float* __restrict__ Whh, const float* __restrict__ bih,
                      const float* __restrict__ bhh, float* __restrict__ H) {
    int b = blockIdx.x;
    int tid = threadIdx.x;  // 320
    int warp = tid >> 5, lane = tid & 31;
    __shared__ __align__(16) float qs[Dv];
    __shared__ __align__(16) float hs[Dv];
    __shared__ float A[Dv];
    __shared__ float hn[Dv];
    for (int i = tid; i < Dv; i += 320) {
        qs[i] = qT[i * 32 + b];
        hs[i] = 0.f;
    }
    __syncthreads();
    for (int r = warp; r < Dv; r += 10) {
        float s = warp_dot300(Wih + (size_t)r * Dv, qs, lane);
        if (lane == 0) A[r] = s + bih[r] + bhh[r];
    }
    __syncthreads();
    for (int k = 0; k < Kv; k++) {
        for (int r = warp; r < Dv; r += 10) {
            float s = warp_dot300(Whh + (size_t)r * Dv, hs, lane);
            if (lane == 0) hn[r] = tanhf(A[r] + s);
        }
        __syncthreads();
        for (int i = tid; i < Dv; i += 320) {
            float v = hn[i];
            hs[i] = v;
            H[(size_t)b * Kv * Dv + k * Dv + i] = v;
        }
        __syncthreads();
    }
}

// ---------------- attention ---------------------------------------------------
__global__ void k_attn(const float* __restrict__ H, const float* __restrict__ V,
                       const int* __restrict__ lengths, float* __restrict__ R) {
    int kk = blockIdx.x, b = blockIdx.y;
    int tid = threadIdx.x;  // 128
    __shared__ __align__(16) float Hs[Dv];
    __shared__ float rbuf[128];
    __shared__ float p[128];
    for (int i = tid; i < Dv; i += 128)
        Hs[i] = H[(size_t)b * Kv * Dv + kk * Dv + i];
    __syncthreads();
    int len = lengths[b];
    float sc = -1e30f;
    if (tid < len) {
        const float* vrow = V + (size_t)(b * Sv + tid) * Dv;
        float s = 0.f;
        for (int d = 0; d < Dv; d += 4) {
            float4 v4 = *(const float4*)&vrow[d];
            s += v4.x * Hs[d] + v4.y * Hs[d + 1] + v4.z * Hs[d + 2] + v4.w * Hs[d + 3];
        }
        sc = s;
    }
    rbuf[tid] = sc;
    __syncthreads();
    for (int s = 64; s > 0; s >>= 1) {
        if (tid < s) rbuf[tid] = fmaxf(rbuf[tid], rbuf[tid + s]);
        __syncthreads();
    }
    float m = rbuf[0];
    __syncthreads();
    float e = (tid < len) ? __expf(sc - m) : 0.f;
    rbuf[tid] = e;
    __syncthreads();
    for (int s = 64; s > 0; s >>= 1) {
        if (tid < s) rbuf[tid] += rbuf[tid + s];
        __syncthreads();
    }
    float denom = rbuf[0];
    __syncthreads();
    p[tid] = e / denom;
    __syncthreads();
    float* out = R + (size_t)(b * Kv + kk) * Dv;
    for (int d = tid; d < Dv; d += 128) {
        float s = 0.f;
        for (int si = 0; si < Sv; si++)
            s += p[si] * V[(size_t)(b * Sv + si) * Dv + d];
        out[d] = s;
    }
}

// ---------------- launch ------------------------------------------------------
extern "C" void kernel_launch(void* const* d_in, const int* in_sizes, int n_in,
                              void* d_out, int out_size) {
    const float* words    = (const float*)d_in[0];
    const int*   lengths  = (const int*)d_in[1];
    const float* vocab    = (const float*)d_in[2];
    const float* dembed   = (const float*)d_in[3];
    const float* W        = (const float*)d_in[4];
    const float* lstm_Wih = (const float*)d_in[5];
    const float* lstm_Whh = (const float*)d_in[6];
    const float* lstm_bih = (const float*)d_in[7];
    const float* lstm_bhh = (const float*)d_in[8];
    const float* rnn_Wih  = (const float*)d_in[9];
    const float* rnn_Whh  = (const float*)d_in[10];
    const float* rnn_bih  = (const float*)d_in[11];
    const float* rnn_bhh  = (const float*)d_in[12];
    float* out = (float*)d_out;

    float *pE, *pRS, *pPL, *pV, *pVP, *pXIT, *pHT, *pH;
    unsigned *pwH, *pwL, *pWH, *pWL, *pXH, *pXL, *pCTH, *pCTL, *pEH, *pEL;
    unsigned *pvoH, *pvoL, *pVH, *pVL, *pWiH, *pWiL;
    cudaGetSymbolAddress((void**)&pE, g_E);
    cudaGetSymbolAddress((void**)&pRS, g_rowsum);
    cudaGetSymbolAddress((void**)&pPL, g_pl);
    cudaGetSymbolAddress((void**)&pV, g_V);
    cudaGetSymbolAddress((void**)&pVP, g_Vpart);
    cudaGetSymbolAddress((void**)&pXIT, g_XIT);
    cudaGetSymbolAddress((void**)&pHT, g_hT);
    cudaGetSymbolAddress((void**)&pH, g_H);
    cudaGetSymbolAddress((void**)&pwH, g_wordsH);
    cudaGetSymbolAddress((void**)&pwL, g_wordsL);
    cudaGetSymbolAddress((void**)&pWH, g_WH);
    cudaGetSymbolAddress((void**)&pWL, g_WL);
    cudaGetSymbolAddress((void**)&pXH, g_XH);
    cudaGetSymbolAddress((void**)&pXL, g_XL);
    cudaGetSymbolAddress((void**)&pCTH, g_CTH);
    cudaGetSymbolAddress((void**)&pCTL, g_CTL);
    cudaGetSymbolAddress((void**)&pEH, g_EH);
    cudaGetSymbolAddress((void**)&pEL, g_EL);
    cudaGetSymbolAddress((void**)&pvoH, g_vocH);
    cudaGetSymbolAddress((void**)&pvoL, g_vocL);
    cudaGetSymbolAddress((void**)&pVH, g_VH);
    cudaGetSymbolAddress((void**)&pVL, g_VL);
    cudaGetSymbolAddress((void**)&pWiH, g_WihTH);
    cudaGetSymbolAddress((void**)&pWiL, g_WihTL);

    cudaFuncSetAttribute(mma_nn, cudaFuncAttributeMaxDynamicSharedMemorySize,
                         MMA_SMEM);
    cudaFuncSetAttribute(k_lstm, cudaFuncAttributeMaxDynamicSharedMemorySize,
                         63488);

    // 0) pre-split operands
    k_splitA<<<(RROWS * 150 + 255) / 256, 256>>>(words, RROWS, Dv, pwH, pwL, 160);
    k_splitB_N<<<(150 * Dv + 255) / 256, 256>>>(W, Dv, Dv, pWH, pWL, 304);
    k_splitB_T<<<dim3((VOC + 1 + 31) / 32, 10), dim3(32, 8)>>>(
        vocab, VOC, Dv, dembed, pCTH, pCTL, ESTRIDE);
    k_splitB_N<<<(10000 * Dv + 255) / 256, 256>>>(vocab, VOC, Dv, pvoH, pvoL,
                                                  304);
    k_splitB_T<<<dim3((G4 + 31) / 32, 10), dim3(32, 8)>>>(
        lstm_Wih, G4, Dv, nullptr, pWiH, pWiL, 1204);

    // 1) X = words @ W  (epi 3: write split packs)
    mma_nn<<<dim3(32, 3, 1), 512, MMA_SMEM>>>(
        pwH, pwL, 160, pWH, pWL, 304, nullptr, nullptr, 0, pXH, pXL, 160, Dv,
        150, 150, 0, 3);

    // 2) logits = X @ CT -> g_E fp32
    mma_nn<<<dim3(32, 157, 1), 512, MMA_SMEM>>>(
        pXH, pXL, 160, pCTH, pCTL, ESTRIDE, nullptr, pE, ESTRIDE, nullptr,
        nullptr, 0, VOC + 1, 150, 150, 0, 0);

    // 3) softmax -> split exp packs + pl + rowsum
    k_softmax<<<RROWS, 256>>>(pE, pEH, pEL, pPL, pRS);

    // 4) V partials (split-K) then reduce + epilogue + split
    mma_nn<<<dim3(32, 3, SPLITK), 512, MMA_SMEM>>>(
        pEH, pEL, 10000, pvoH, pvoL, 304, nullptr, pVP, VPART_LD, nullptr,
        nullptr, 0, Dv, KSPL2, 10000, (size_t)RROWS * VPART_LD, 2);
    k_vreduce<<<(RROWS * 150 + 255) / 256, 256>>>(pVP, pPL, pRS, words, pV, pVH,
                                                  pVL);

    // 5) XI = V @ WihT + bih -> XIT (epi 4: transposed scatter)
    mma_nn<<<dim3(32, 10, 1), 512, MMA_SMEM>>>(
        pVH, pVL, 160, pWiH, pWiL, 1204, lstm_bih, pXIT, 0, nullptr, nullptr, 0,
        G4, 150, 150, 0, 4);

    // 6) persistent LSTM
    k_init<<<(Dv * Bv + 255) / 256, 256>>>();
    k_lstm<<<NC_LSTM, 256, 63488>>>(pXIT, lstm_Whh, lstm_bhh, lengths);

    // 7) RNN readout (q = final hT in g_hT[0])
    k_rnn<<<Bv, 320>>>(pHT, rnn_Wih, rnn_Whh, rnn_bih, rnn_bhh, pH);

    // 8) attention -> output
    k_attn<<<dim3(Kv, Bv), 128>>>(pH, pV, lengths, out);
}